// round 7
// baseline (speedup 1.0000x reference)
#include <cuda_runtime.h>
#include <cuda_fp16.h>
#include <cstdint>

#define N_NODES 50000
#define N_EDGES 800000
#define HDIM 128
#define DDIM 32
#define CDIM 64
#define RDIM 8

// ---- scratch (device globals; no allocation in kernel_launch) ----
__device__ float  g_hbuf[N_NODES * DDIM];         // h          [N,32] fp32
__device__ __half g_cbuf[N_NODES * RDIM * DDIM];  // c          [N*R,32] fp16
__device__ float  g_agg[N_NODES * DDIM];          // segsum     [N,32]

__device__ __forceinline__ float silu_f(float v) { return v / (1.0f + __expf(-v)); }

__device__ __forceinline__ uint32_t f2tf32(float f) {
    uint32_t u;
    asm("cvt.rna.tf32.f32 %0, %1;" : "=r"(u) : "f"(f));
    return u;
}

__device__ __forceinline__ void mma_tf32(float d[4], uint32_t a0, uint32_t a1,
                                         uint32_t a2, uint32_t a3,
                                         uint32_t b0, uint32_t b1) {
    asm volatile(
        "mma.sync.aligned.m16n8k8.row.col.f32.tf32.tf32.f32 "
        "{%0,%1,%2,%3},{%4,%5,%6,%7},{%8,%9},{%0,%1,%2,%3};"
        : "+f"(d[0]), "+f"(d[1]), "+f"(d[2]), "+f"(d[3])
        : "r"(a0), "r"(a1), "r"(a2), "r"(a3), "r"(b0), "r"(b1));
}

__device__ __forceinline__ void red_v4(float* p, float4 v) {
    asm volatile("red.global.add.v4.f32 [%0], {%1,%2,%3,%4};"
                 :: "l"(p), "f"(v.x), "f"(v.y), "f"(v.z), "f"(v.w) : "memory");
}

// Fused 2-layer MLP: Y[M,32] = silu(silu(A[M,K])@W1[K,128] (+b1)) @ W2[128,32] (+b2)
// Grid-stride persistent; W1/W2 in tf32 smem once per block. OutT = float or __half.
template<int K, bool BIAS, typename OutT>
__global__ void __launch_bounds__(256) fused_mlp_kernel(
    const float* __restrict__ A, const float* __restrict__ W1,
    const float* __restrict__ b1, const float* __restrict__ W2,
    const float* __restrict__ b2, OutT* __restrict__ Y, int M)
{
    extern __shared__ uint32_t sm[];
    uint32_t* W1s = sm;                        // [K][136] tf32
    uint32_t* C1s = W1s + K * 136;             // [128][132] tf32 (per-warp private rows)
    uint32_t* W2s = C1s + 128 * 132;           // [128][40] tf32
    float* b1s = (float*)(W2s + 128 * 40);     // [128]
    float* b2s = b1s + 128;                    // [32]

    const int tid = threadIdx.x;

    for (int i = tid; i < K * 128; i += 256) {
        int k = i >> 7, n = i & 127;
        W1s[k * 136 + n] = f2tf32(W1[i]);
    }
    for (int i = tid; i < 128 * 32; i += 256) {
        int k = i >> 5, n = i & 31;
        W2s[k * 40 + n] = f2tf32(W2[i]);
    }
    if (tid < 128) b1s[tid] = BIAS ? b1[tid] : 0.0f;
    if (tid < 32)  b2s[tid] = BIAS ? b2[tid] : 0.0f;
    __syncthreads();

    const int w = tid >> 5, lane = tid & 31;
    const int g = lane >> 2, tig = lane & 3;
    const int row0 = w * 16 + g, row1 = w * 16 + g + 8;
    const int ntiles = (M + 127) / 128;

    for (int tile = blockIdx.x; tile < ntiles; tile += gridDim.x) {
        const int m0 = tile * 128 + w * 16;
        const int r0 = m0 + g, r1 = m0 + g + 8;
        const bool v0 = r0 < M, v1 = r1 < M;
        const float* A0 = A + (size_t)r0 * K;
        const float* A1 = A + (size_t)r1 * K;

        // prefetch + convert ALL phase-1 A fragments (batched LDGs, high MLP)
        uint32_t af[K / 8][4];
#pragma unroll
        for (int kt = 0; kt < K / 8; kt++) {
            const int c0 = kt * 8 + tig;
            float f0 = v0 ? A0[c0]     : 0.0f;
            float f1 = v1 ? A1[c0]     : 0.0f;
            float f2 = v0 ? A0[c0 + 4] : 0.0f;
            float f3 = v1 ? A1[c0 + 4] : 0.0f;
            af[kt][0] = f2tf32(silu_f(f0));
            af[kt][1] = f2tf32(silu_f(f1));
            af[kt][2] = f2tf32(silu_f(f2));
            af[kt][3] = f2tf32(silu_f(f3));
        }

        // ---------------- phase 1: H = silu(A)@W1 ----------------
        float acc1[16][4];
#pragma unroll
        for (int nt = 0; nt < 16; nt++)
#pragma unroll
            for (int j = 0; j < 4; j++) acc1[nt][j] = 0.0f;

#pragma unroll
        for (int kt = 0; kt < K / 8; kt++) {
            const int c0 = kt * 8 + tig;
#pragma unroll
            for (int nt = 0; nt < 16; nt++) {
                uint32_t b0  = W1s[c0 * 136 + nt * 8 + g];
                uint32_t b1r = W1s[(c0 + 4) * 136 + nt * 8 + g];
                mma_tf32(acc1[nt], af[kt][0], af[kt][1], af[kt][2], af[kt][3], b0, b1r);
            }
        }

        // store H tile (bias + silu, tf32) into this warp's private C1s rows
#pragma unroll
        for (int nt = 0; nt < 16; nt++) {
            int cA = nt * 8 + 2 * tig;
            C1s[row0 * 132 + cA]     = f2tf32(silu_f(acc1[nt][0] + b1s[cA]));
            C1s[row0 * 132 + cA + 1] = f2tf32(silu_f(acc1[nt][1] + b1s[cA + 1]));
            C1s[row1 * 132 + cA]     = f2tf32(silu_f(acc1[nt][2] + b1s[cA]));
            C1s[row1 * 132 + cA + 1] = f2tf32(silu_f(acc1[nt][3] + b1s[cA + 1]));
        }
        __syncwarp();

        // ---------------- phase 2: Y = silu(H)@W2 ----------------
        float acc2[4][4];
#pragma unroll
        for (int nt = 0; nt < 4; nt++)
#pragma unroll
            for (int j = 0; j < 4; j++) acc2[nt][j] = 0.0f;

#pragma unroll
        for (int kt = 0; kt < 16; kt++) {
            const int c0 = kt * 8 + tig;
            uint32_t a0 = C1s[row0 * 132 + c0];
            uint32_t a1 = C1s[row1 * 132 + c0];
            uint32_t a2 = C1s[row0 * 132 + c0 + 4];
            uint32_t a3 = C1s[row1 * 132 + c0 + 4];
#pragma unroll
            for (int nt = 0; nt < 4; nt++) {
                uint32_t b0  = W2s[c0 * 40 + nt * 8 + g];
                uint32_t b1r = W2s[(c0 + 4) * 40 + nt * 8 + g];
                mma_tf32(acc2[nt], a0, a1, a2, a3, b0, b1r);
            }
        }

#pragma unroll
        for (int nt = 0; nt < 4; nt++) {
            int cA = nt * 8 + 2 * tig;
            if constexpr (sizeof(OutT) == 2) {
                __half2* Y2 = (__half2*)Y;
                if (v0) Y2[((size_t)r0 * 32 + cA) >> 1] =
                    __floats2half2_rn(acc2[nt][0] + b2s[cA], acc2[nt][1] + b2s[cA + 1]);
                if (v1) Y2[((size_t)r1 * 32 + cA) >> 1] =
                    __floats2half2_rn(acc2[nt][2] + b2s[cA], acc2[nt][3] + b2s[cA + 1]);
            } else {
                float* Yf = (float*)Y;
                if (v0) {
                    Yf[(size_t)r0 * 32 + cA]     = acc2[nt][0] + b2s[cA];
                    Yf[(size_t)r0 * 32 + cA + 1] = acc2[nt][1] + b2s[cA + 1];
                }
                if (v1) {
                    Yf[(size_t)r1 * 32 + cA]     = acc2[nt][2] + b2s[cA];
                    Yf[(size_t)r1 * 32 + cA + 1] = acc2[nt][3] + b2s[cA + 1];
                }
            }
        }
        __syncwarp();   // phase-2 reads done before next tile overwrites C1s
    }
}

// FFMA GEMM (final up-projection): Y[M,NC] = A[M,K]@W[K,NC]
template<int K, int NC, int TM, bool SILU, bool BIAS>
__global__ void __launch_bounds__((NC/4)*(TM/8)) gemm_silu_kernel(
    const float* __restrict__ A, const float* __restrict__ W,
    const float* __restrict__ bias, float* __restrict__ Y, int M)
{
    __shared__ float As[TM][33];
    __shared__ float Ws[32][NC];
    const int tx = threadIdx.x;
    const int ty = threadIdx.y;
    const int TH = (NC/4)*(TM/8);
    const int tid = ty*(NC/4) + tx;
    const int m0 = blockIdx.x * TM;

    float acc[8][4];
#pragma unroll
    for (int i = 0; i < 8; i++)
#pragma unroll
        for (int j = 0; j < 4; j++) acc[i][j] = 0.0f;

    for (int k0 = 0; k0 < K; k0 += 32) {
        for (int idx = tid; idx < TM*8; idx += TH) {
            int row = idx >> 3, cc = idx & 7;
            float4 v = make_float4(0.f, 0.f, 0.f, 0.f);
            int m = m0 + row;
            if (m < M && (k0 + cc*4) < K) v = *(const float4*)(A + (size_t)m * K + k0 + cc*4);
            if (SILU) { v.x = silu_f(v.x); v.y = silu_f(v.y); v.z = silu_f(v.z); v.w = silu_f(v.w); }
            As[row][cc*4+0] = v.x; As[row][cc*4+1] = v.y;
            As[row][cc*4+2] = v.z; As[row][cc*4+3] = v.w;
        }
        for (int idx = tid; idx < 8*NC; idx += TH) {
            int kk = idx / (NC/4), cc = idx % (NC/4);
            float4 wv = make_float4(0.f,0.f,0.f,0.f);
            if (k0 + kk < K) wv = *(const float4*)(W + (size_t)(k0+kk)*NC + cc*4);
            *(float4*)&Ws[kk][cc*4] = wv;
        }
        __syncthreads();
#pragma unroll 8
        for (int kk = 0; kk < 32; kk++) {
            float4 wv = *(const float4*)&Ws[kk][tx*4];
#pragma unroll
            for (int i = 0; i < 8; i++) {
                float a = As[ty*8+i][kk];
                acc[i][0] = fmaf(a, wv.x, acc[i][0]);
                acc[i][1] = fmaf(a, wv.y, acc[i][1]);
                acc[i][2] = fmaf(a, wv.z, acc[i][2]);
                acc[i][3] = fmaf(a, wv.w, acc[i][3]);
            }
        }
        __syncthreads();
    }

    float4 bv = make_float4(0.f, 0.f, 0.f, 0.f);
    if (BIAS) bv = *(const float4*)(bias + tx*4);
#pragma unroll
    for (int i = 0; i < 8; i++) {
        int m = m0 + ty*8 + i;
        if (m < M) {
            float4 o = make_float4(acc[i][0]+bv.x, acc[i][1]+bv.y,
                                   acc[i][2]+bv.z, acc[i][3]+bv.w);
            *(float4*)(Y + (size_t)m * NC + tx*4) = o;
        }
    }
}

// One warp per edge; c stored fp16 -> each c row is ONE 512B contiguous sweep
// read as 2x LDG.64 per lane (2 lines per instruction, 4 wavefronts/row).
// Lane l owns cols 4*(l&7)..+3 of rA = l>>3 (chunk A) and rB = rA+4 (chunk B)
// -- identical ownership to the fp32 version, so reductions are unchanged.
__global__ void edge_kernel(const __half* __restrict__ c, const float* __restrict__ h,
                            const float* __restrict__ rbfs, const int* __restrict__ ei,
                            float* __restrict__ agg)
{
    int gwarp = blockIdx.x * 8 + (threadIdx.x >> 5);
    if (gwarp >= N_EDGES) return;
    const int lane = threadIdx.x & 31;
    const int grp = lane >> 3;          // rA = grp, rB = grp+4
    const int col4 = lane & 7;          // owns cols col4*4 .. col4*4+3

    const int src = ei[gwarp];
    const int dst = ei[N_EDGES + gwarp];

    const uint2* cu = (const uint2*)c;              // 1 uint2 = 4 halfs
    const size_t db = (size_t)dst * 64;             // row = 256 halfs = 64 uint2
    const size_t sb = (size_t)src * 64;
    const int offA = grp * 8 + col4;                // (grp*32 + col4*4)/4
    const int offB = 32 + offA;                     // ((grp+4)*32 + col4*4)/4

    uint2 du0 = cu[db + offA], du1 = cu[db + offB];
    uint2 su0 = cu[sb + offA], su1 = cu[sb + offB];

    float2 dA0 = __half22float2(*(__half2*)&du0.x), dA1 = __half22float2(*(__half2*)&du0.y);
    float2 dB0 = __half22float2(*(__half2*)&du1.x), dB1 = __half22float2(*(__half2*)&du1.y);
    float2 sA0 = __half22float2(*(__half2*)&su0.x), sA1 = __half22float2(*(__half2*)&su0.y);
    float2 sB0 = __half22float2(*(__half2*)&su1.x), sB1 = __half22float2(*(__half2*)&su1.y);

    float ceA[4], ceB[4];
    ceA[0] = dA0.x * (sA0.x + 1.0f); ceA[1] = dA0.y * (sA0.y + 1.0f);
    ceA[2] = dA1.x * (sA1.x + 1.0f); ceA[3] = dA1.y * (sA1.y + 1.0f);
    ceB[0] = dB0.x * (sB0.x + 1.0f); ceB[1] = dB0.y * (sB0.y + 1.0f);
    ceB[2] = dB1.x * (sB1.x + 1.0f); ceB[3] = dB1.y * (sB1.y + 1.0f);

    // per-r sumsq over the 8 lanes of each group (masks 1,2,4), both r's packed
    float ssA = 0.f, ssB = 0.f;
#pragma unroll
    for (int j = 0; j < 4; j++) { ssA = fmaf(ceA[j], ceA[j], ssA); ssB = fmaf(ceB[j], ceB[j], ssB); }
#pragma unroll
    for (int mask = 1; mask <= 4; mask <<= 1) {
        ssA += __shfl_xor_sync(0xffffffffu, ssA, mask);
        ssB += __shfl_xor_sync(0xffffffffu, ssB, mask);
    }
    float invA = rsqrtf(fmaxf(ssA, 1e-24f));
    float invB = rsqrtf(fmaxf(ssB, 1e-24f));

    // rbf: one 8-lane load + 2 shuffles
    float rv = (lane < 8) ? rbfs[(size_t)gwarp * RDIM + lane] : 0.0f;
    float rbA = __shfl_sync(0xffffffffu, rv, grp);
    float rbB = __shfl_sync(0xffffffffu, rv, grp + 4);

    float sA = rbA * invA, sB = rbB * invB;
    float wl[4];
#pragma unroll
    for (int j = 0; j < 4; j++) wl[j] = ceA[j] * sA + ceB[j] * sB;
#pragma unroll
    for (int mask = 8; mask <= 16; mask <<= 1)
#pragma unroll
        for (int j = 0; j < 4; j++) wl[j] += __shfl_xor_sync(0xffffffffu, wl[j], mask);

    // w-norm over the 8 distinct col-groups (masks 1,2,4)
    float sq = 0.f;
#pragma unroll
    for (int j = 0; j < 4; j++) sq = fmaf(wl[j], wl[j], sq);
#pragma unroll
    for (int mask = 1; mask <= 4; mask <<= 1)
        sq += __shfl_xor_sync(0xffffffffu, sq, mask);
    float invw = rsqrtf(fmaxf(sq, 1e-24f));

    if (grp == 0) {
        const float4 hv = *(const float4*)(h + (size_t)dst * DDIM + col4 * 4);
        float4 m = make_float4(hv.x * wl[0] * invw, hv.y * wl[1] * invw,
                               hv.z * wl[2] * invw, hv.w * wl[3] * invw);
        red_v4(agg + (size_t)src * DDIM + col4 * 4, m);
    }
}

__global__ void zero_kernel(float4* p, int n4) {
    int i = blockIdx.x * blockDim.x + threadIdx.x;
    if (i < n4) p[i] = make_float4(0.f, 0.f, 0.f, 0.f);
}

extern "C" void kernel_launch(void* const* d_in, const int* in_sizes, int n_in,
                              void* d_out, int out_size)
{
    const float* x      = (const float*)d_in[0];
    const float* rbfs   = (const float*)d_in[1];
    const float* coeffs = (const float*)d_in[2];
    const float* W1     = (const float*)d_in[3];
    const float* b1     = (const float*)d_in[4];
    const float* W2     = (const float*)d_in[5];
    const float* b2     = (const float*)d_in[6];
    const float* Wc1    = (const float*)d_in[7];
    const float* Wc2    = (const float*)d_in[8];
    const float* Wu     = (const float*)d_in[9];
    const int*   ei     = (const int*)d_in[10];
    float* out = (float*)d_out;

    float *hbuf, *agg;
    __half* cbuf;
    cudaGetSymbolAddress((void**)&hbuf, g_hbuf);
    cudaGetSymbolAddress((void**)&cbuf, g_cbuf);
    cudaGetSymbolAddress((void**)&agg,  g_agg);

    const int MR = N_NODES * RDIM;

    const int smem_c = (CDIM * 136 + 128 * 132 + 128 * 40 + 160) * 4;   // K=64
    const int smem_n = (HDIM * 136 + 128 * 132 + 128 * 40 + 160) * 4;   // K=128
    cudaFuncSetAttribute(fused_mlp_kernel<CDIM, false, __half>,
                         cudaFuncAttributeMaxDynamicSharedMemorySize, smem_c);
    cudaFuncSetAttribute(fused_mlp_kernel<HDIM, true, float>,
                         cudaFuncAttributeMaxDynamicSharedMemorySize, smem_n);

    // coeffs path: c = silu(silu(coeffs)@Wc1)@Wc2 -> fp16   (M = 400000)
    fused_mlp_kernel<CDIM, false, __half><<<148, 256, smem_c>>>(
        coeffs, Wc1, nullptr, Wc2, nullptr, cbuf, MR);

    // node path: h = silu(silu(x)@W1+b1)@W2+b2 -> fp32
    fused_mlp_kernel<HDIM, true, float><<<148, 256, smem_n>>>(
        x, W1, b1, W2, b2, hbuf, N_NODES);

    // zero aggregation buffer
    zero_kernel<<<((N_NODES*DDIM/4) + 255)/256, 256>>>((float4*)agg, N_NODES*DDIM/4);

    // edge stage + v4 reduction segment-sum into agg
    edge_kernel<<<N_EDGES/8, 256>>>(cbuf, hbuf, rbfs, ei, agg);

    // out = agg @ Wu
    gemm_silu_kernel<32,128,64,false,false>
        <<<(N_NODES + 63)/64, dim3(32,8)>>>(agg, Wu, nullptr, out, N_NODES);
}

// round 8
// speedup vs baseline: 1.4715x; 1.4715x over previous
#include <cuda_runtime.h>
#include <cstdint>

#define N_NODES 50000
#define N_EDGES 800000
#define HDIM 128
#define DDIM 32
#define CDIM 64
#define RDIM 8

// ---- scratch (device globals; no allocation in kernel_launch) ----
__device__ float g_hbuf[N_NODES * DDIM];        // h                    [N,32]
__device__ float g_cbuf[N_NODES * RDIM * DDIM]; // c                    [N*R,32]
__device__ float g_agg[N_NODES * DDIM];         // segment_sum target   [N,32]

__device__ __forceinline__ float silu_f(float v) { return v / (1.0f + __expf(-v)); }

__device__ __forceinline__ uint32_t f2tf32(float f) {
    uint32_t u;
    asm("cvt.rna.tf32.f32 %0, %1;" : "=r"(u) : "f"(f));
    return u;
}

__device__ __forceinline__ void mma_tf32(float d[4], uint32_t a0, uint32_t a1,
                                         uint32_t a2, uint32_t a3,
                                         uint32_t b0, uint32_t b1) {
    asm volatile(
        "mma.sync.aligned.m16n8k8.row.col.f32.tf32.tf32.f32 "
        "{%0,%1,%2,%3},{%4,%5,%6,%7},{%8,%9},{%0,%1,%2,%3};"
        : "+f"(d[0]), "+f"(d[1]), "+f"(d[2]), "+f"(d[3])
        : "r"(a0), "r"(a1), "r"(a2), "r"(a3), "r"(b0), "r"(b1));
}

__device__ __forceinline__ void red_v4(float* p, float4 v) {
    asm volatile("red.global.add.v4.f32 [%0], {%1,%2,%3,%4};"
                 :: "l"(p), "f"(v.x), "f"(v.y), "f"(v.z), "f"(v.w) : "memory");
}

// Fused 2-layer MLP: Y[M,32] = silu(silu(A[M,K])@W1[K,128] (+b1)) @ W2[128,32] (+b2)
// Grid-stride persistent; W1/W2 in tf32 smem once per block.
template<int K, bool BIAS>
__global__ void __launch_bounds__(256) fused_mlp_kernel(
    const float* __restrict__ A, const float* __restrict__ W1,
    const float* __restrict__ b1, const float* __restrict__ W2,
    const float* __restrict__ b2, float* __restrict__ Y, int M)
{
    extern __shared__ uint32_t sm[];
    uint32_t* W1s = sm;                        // [K][136] tf32
    uint32_t* C1s = W1s + K * 136;             // [128][132] tf32 (per-warp private rows)
    uint32_t* W2s = C1s + 128 * 132;           // [128][40] tf32
    float* b1s = (float*)(W2s + 128 * 40);     // [128]
    float* b2s = b1s + 128;                    // [32]

    const int tid = threadIdx.x;

    for (int i = tid; i < K * 128; i += 256) {
        int k = i >> 7, n = i & 127;
        W1s[k * 136 + n] = f2tf32(W1[i]);
    }
    for (int i = tid; i < 128 * 32; i += 256) {
        int k = i >> 5, n = i & 31;
        W2s[k * 40 + n] = f2tf32(W2[i]);
    }
    if (tid < 128) b1s[tid] = BIAS ? b1[tid] : 0.0f;
    if (tid < 32)  b2s[tid] = BIAS ? b2[tid] : 0.0f;
    __syncthreads();

    const int w = tid >> 5, lane = tid & 31;
    const int g = lane >> 2, tig = lane & 3;
    const int row0 = w * 16 + g, row1 = w * 16 + g + 8;
    const int ntiles = (M + 127) / 128;

    for (int tile = blockIdx.x; tile < ntiles; tile += gridDim.x) {
        const int m0 = tile * 128 + w * 16;
        const int r0 = m0 + g, r1 = m0 + g + 8;
        const bool v0 = r0 < M, v1 = r1 < M;
        const float* A0 = A + (size_t)r0 * K;
        const float* A1 = A + (size_t)r1 * K;

        // prefetch + convert ALL phase-1 A fragments (batched LDGs, high MLP)
        uint32_t af[K / 8][4];
#pragma unroll
        for (int kt = 0; kt < K / 8; kt++) {
            const int c0 = kt * 8 + tig;
            float f0 = v0 ? A0[c0]     : 0.0f;
            float f1 = v1 ? A1[c0]     : 0.0f;
            float f2 = v0 ? A0[c0 + 4] : 0.0f;
            float f3 = v1 ? A1[c0 + 4] : 0.0f;
            af[kt][0] = f2tf32(silu_f(f0));
            af[kt][1] = f2tf32(silu_f(f1));
            af[kt][2] = f2tf32(silu_f(f2));
            af[kt][3] = f2tf32(silu_f(f3));
        }

        // ---------------- phase 1: H = silu(A)@W1 ----------------
        float acc1[16][4];
#pragma unroll
        for (int nt = 0; nt < 16; nt++)
#pragma unroll
            for (int j = 0; j < 4; j++) acc1[nt][j] = 0.0f;

#pragma unroll
        for (int kt = 0; kt < K / 8; kt++) {
            const int c0 = kt * 8 + tig;
#pragma unroll
            for (int nt = 0; nt < 16; nt++) {
                uint32_t b0  = W1s[c0 * 136 + nt * 8 + g];
                uint32_t b1r = W1s[(c0 + 4) * 136 + nt * 8 + g];
                mma_tf32(acc1[nt], af[kt][0], af[kt][1], af[kt][2], af[kt][3], b0, b1r);
            }
        }

        // store H tile (bias + silu, tf32) into this warp's private C1s rows
#pragma unroll
        for (int nt = 0; nt < 16; nt++) {
            int cA = nt * 8 + 2 * tig;
            C1s[row0 * 132 + cA]     = f2tf32(silu_f(acc1[nt][0] + b1s[cA]));
            C1s[row0 * 132 + cA + 1] = f2tf32(silu_f(acc1[nt][1] + b1s[cA + 1]));
            C1s[row1 * 132 + cA]     = f2tf32(silu_f(acc1[nt][2] + b1s[cA]));
            C1s[row1 * 132 + cA + 1] = f2tf32(silu_f(acc1[nt][3] + b1s[cA + 1]));
        }
        __syncwarp();

        // ---------------- phase 2: Y = silu(H)@W2 ----------------
        float acc2[4][4];
#pragma unroll
        for (int nt = 0; nt < 4; nt++)
#pragma unroll
            for (int j = 0; j < 4; j++) acc2[nt][j] = 0.0f;

#pragma unroll
        for (int kt = 0; kt < 16; kt++) {
            const int c0 = kt * 8 + tig;
            uint32_t a0 = C1s[row0 * 132 + c0];
            uint32_t a1 = C1s[row1 * 132 + c0];
            uint32_t a2 = C1s[row0 * 132 + c0 + 4];
            uint32_t a3 = C1s[row1 * 132 + c0 + 4];
#pragma unroll
            for (int nt = 0; nt < 4; nt++) {
                uint32_t b0  = W2s[c0 * 40 + nt * 8 + g];
                uint32_t b1r = W2s[(c0 + 4) * 40 + nt * 8 + g];
                mma_tf32(acc2[nt], a0, a1, a2, a3, b0, b1r);
            }
        }

#pragma unroll
        for (int nt = 0; nt < 4; nt++) {
            int cA = nt * 8 + 2 * tig;
            if (v0) {
                Y[(size_t)r0 * 32 + cA]     = acc2[nt][0] + b2s[cA];
                Y[(size_t)r0 * 32 + cA + 1] = acc2[nt][1] + b2s[cA + 1];
            }
            if (v1) {
                Y[(size_t)r1 * 32 + cA]     = acc2[nt][2] + b2s[cA];
                Y[(size_t)r1 * 32 + cA + 1] = acc2[nt][3] + b2s[cA + 1];
            }
        }
        __syncwarp();   // phase-2 reads done before next tile overwrites C1s
    }
}

// FFMA GEMM (final up-projection): Y[M,NC] = A[M,K]@W[K,NC]
template<int K, int NC, int TM, bool SILU, bool BIAS>
__global__ void __launch_bounds__((NC/4)*(TM/8)) gemm_silu_kernel(
    const float* __restrict__ A, const float* __restrict__ W,
    const float* __restrict__ bias, float* __restrict__ Y, int M)
{
    __shared__ float As[TM][33];
    __shared__ float Ws[32][NC];
    const int tx = threadIdx.x;
    const int ty = threadIdx.y;
    const int TH = (NC/4)*(TM/8);
    const int tid = ty*(NC/4) + tx;
    const int m0 = blockIdx.x * TM;

    float acc[8][4];
#pragma unroll
    for (int i = 0; i < 8; i++)
#pragma unroll
        for (int j = 0; j < 4; j++) acc[i][j] = 0.0f;

    for (int k0 = 0; k0 < K; k0 += 32) {
        for (int idx = tid; idx < TM*8; idx += TH) {
            int row = idx >> 3, cc = idx & 7;
            float4 v = make_float4(0.f, 0.f, 0.f, 0.f);
            int m = m0 + row;
            if (m < M && (k0 + cc*4) < K) v = *(const float4*)(A + (size_t)m * K + k0 + cc*4);
            if (SILU) { v.x = silu_f(v.x); v.y = silu_f(v.y); v.z = silu_f(v.z); v.w = silu_f(v.w); }
            As[row][cc*4+0] = v.x; As[row][cc*4+1] = v.y;
            As[row][cc*4+2] = v.z; As[row][cc*4+3] = v.w;
        }
        for (int idx = tid; idx < 8*NC; idx += TH) {
            int kk = idx / (NC/4), cc = idx % (NC/4);
            float4 wv = make_float4(0.f,0.f,0.f,0.f);
            if (k0 + kk < K) wv = *(const float4*)(W + (size_t)(k0+kk)*NC + cc*4);
            *(float4*)&Ws[kk][cc*4] = wv;
        }
        __syncthreads();
#pragma unroll 8
        for (int kk = 0; kk < 32; kk++) {
            float4 wv = *(const float4*)&Ws[kk][tx*4];
#pragma unroll
            for (int i = 0; i < 8; i++) {
                float a = As[ty*8+i][kk];
                acc[i][0] = fmaf(a, wv.x, acc[i][0]);
                acc[i][1] = fmaf(a, wv.y, acc[i][1]);
                acc[i][2] = fmaf(a, wv.z, acc[i][2]);
                acc[i][3] = fmaf(a, wv.w, acc[i][3]);
            }
        }
        __syncthreads();
    }

    float4 bv = make_float4(0.f, 0.f, 0.f, 0.f);
    if (BIAS) bv = *(const float4*)(bias + tx*4);
#pragma unroll
    for (int i = 0; i < 8; i++) {
        int m = m0 + ty*8 + i;
        if (m < M) {
            float4 o = make_float4(acc[i][0]+bv.x, acc[i][1]+bv.y,
                                   acc[i][2]+bv.z, acc[i][3]+bv.w);
            *(float4*)(Y + (size_t)m * NC + tx*4) = o;
        }
    }
}

// TWO edges per warp, coalesced fp32 c loads (8 LDG.128 in flight per warp).
// Per edge: lane l reads float4 #l and #(32+l) of the 256-float c rows.
// Lane l owns cols 4*(l&7)..+3 of rA = l>>3 and rB = rA+4.
__global__ void edge_kernel(const float* __restrict__ c, const float* __restrict__ h,
                            const float* __restrict__ rbfs, const int* __restrict__ ei,
                            float* __restrict__ agg)
{
    int gwarp = blockIdx.x * 8 + (threadIdx.x >> 5);
    const int e0 = gwarp * 2;
    if (e0 >= N_EDGES) return;
    const int e1 = e0 + 1;
    const int lane = threadIdx.x & 31;
    const int grp = lane >> 3;          // rA = grp, rB = grp+4
    const int col4 = lane & 7;          // owns cols col4*4 .. col4*4+3

    const int src0 = ei[e0],           src1 = ei[e1];
    const int dst0 = ei[N_EDGES + e0], dst1 = ei[N_EDGES + e1];

    const float4* c4 = (const float4*)c;
    const size_t db0 = (size_t)dst0 * 64, sb0 = (size_t)src0 * 64;
    const size_t db1 = (size_t)dst1 * 64, sb1 = (size_t)src1 * 64;

    // issue ALL gathers up-front (8 independent LDG.128 per lane)
    float4 d00 = c4[db0 + lane], d01 = c4[db0 + 32 + lane];
    float4 s00 = c4[sb0 + lane], s01 = c4[sb0 + 32 + lane];
    float4 d10 = c4[db1 + lane], d11 = c4[db1 + 32 + lane];
    float4 s10 = c4[sb1 + lane], s11 = c4[sb1 + 32 + lane];

    // one coalesced rbf load covers both edges (rows e0,e1 are contiguous)
    float rv = (lane < 16) ? rbfs[(size_t)e0 * RDIM + lane] : 0.0f;

#pragma unroll
    for (int e = 0; e < 2; e++) {
        float4 da = (e == 0) ? d00 : d10;
        float4 dbv = (e == 0) ? d01 : d11;
        float4 sa = (e == 0) ? s00 : s10;
        float4 sbv = (e == 0) ? s01 : s11;

        float ceA[4], ceB[4];
        ceA[0] = da.x * (sa.x + 1.0f);  ceA[1] = da.y * (sa.y + 1.0f);
        ceA[2] = da.z * (sa.z + 1.0f);  ceA[3] = da.w * (sa.w + 1.0f);
        ceB[0] = dbv.x * (sbv.x + 1.0f); ceB[1] = dbv.y * (sbv.y + 1.0f);
        ceB[2] = dbv.z * (sbv.z + 1.0f); ceB[3] = dbv.w * (sbv.w + 1.0f);

        // per-r sumsq (masks 1,2,4), both r's packed
        float ssA = 0.f, ssB = 0.f;
#pragma unroll
        for (int j = 0; j < 4; j++) { ssA = fmaf(ceA[j], ceA[j], ssA); ssB = fmaf(ceB[j], ceB[j], ssB); }
#pragma unroll
        for (int mask = 1; mask <= 4; mask <<= 1) {
            ssA += __shfl_xor_sync(0xffffffffu, ssA, mask);
            ssB += __shfl_xor_sync(0xffffffffu, ssB, mask);
        }
        float invA = rsqrtf(fmaxf(ssA, 1e-24f));
        float invB = rsqrtf(fmaxf(ssB, 1e-24f));

        float rbA = __shfl_sync(0xffffffffu, rv, e * 8 + grp);
        float rbB = __shfl_sync(0xffffffffu, rv, e * 8 + grp + 4);

        float sA = rbA * invA, sB = rbB * invB;
        float wl[4];
#pragma unroll
        for (int j = 0; j < 4; j++) wl[j] = ceA[j] * sA + ceB[j] * sB;
#pragma unroll
        for (int mask = 8; mask <= 16; mask <<= 1)
#pragma unroll
            for (int j = 0; j < 4; j++) wl[j] += __shfl_xor_sync(0xffffffffu, wl[j], mask);

        // w-norm over the 8 col-groups (masks 1,2,4)
        float sq = 0.f;
#pragma unroll
        for (int j = 0; j < 4; j++) sq = fmaf(wl[j], wl[j], sq);
#pragma unroll
        for (int mask = 1; mask <= 4; mask <<= 1)
            sq += __shfl_xor_sync(0xffffffffu, sq, mask);
        float invw = rsqrtf(fmaxf(sq, 1e-24f));

        if (grp == 0) {
            const int dste = (e == 0) ? dst0 : dst1;
            const int srce = (e == 0) ? src0 : src1;
            const float4 hv = *(const float4*)(h + (size_t)dste * DDIM + col4 * 4);
            float4 m = make_float4(hv.x * wl[0] * invw, hv.y * wl[1] * invw,
                                   hv.z * wl[2] * invw, hv.w * wl[3] * invw);
            red_v4(agg + (size_t)srce * DDIM + col4 * 4, m);
        }
    }
}

__global__ void zero_kernel(float4* p, int n4) {
    int i = blockIdx.x * blockDim.x + threadIdx.x;
    if (i < n4) p[i] = make_float4(0.f, 0.f, 0.f, 0.f);
}

extern "C" void kernel_launch(void* const* d_in, const int* in_sizes, int n_in,
                              void* d_out, int out_size)
{
    const float* x      = (const float*)d_in[0];
    const float* rbfs   = (const float*)d_in[1];
    const float* coeffs = (const float*)d_in[2];
    const float* W1     = (const float*)d_in[3];
    const float* b1     = (const float*)d_in[4];
    const float* W2     = (const float*)d_in[5];
    const float* b2     = (const float*)d_in[6];
    const float* Wc1    = (const float*)d_in[7];
    const float* Wc2    = (const float*)d_in[8];
    const float* Wu     = (const float*)d_in[9];
    const int*   ei     = (const int*)d_in[10];
    float* out = (float*)d_out;

    float *hbuf, *cbuf, *agg;
    cudaGetSymbolAddress((void**)&hbuf, g_hbuf);
    cudaGetSymbolAddress((void**)&cbuf, g_cbuf);
    cudaGetSymbolAddress((void**)&agg,  g_agg);

    const int MR = N_NODES * RDIM;

    const int smem_c = (CDIM * 136 + 128 * 132 + 128 * 40 + 160) * 4;   // K=64
    const int smem_n = (HDIM * 136 + 128 * 132 + 128 * 40 + 160) * 4;   // K=128
    cudaFuncSetAttribute(fused_mlp_kernel<CDIM, false>,
                         cudaFuncAttributeMaxDynamicSharedMemorySize, smem_c);
    cudaFuncSetAttribute(fused_mlp_kernel<HDIM, true>,
                         cudaFuncAttributeMaxDynamicSharedMemorySize, smem_n);

    // coeffs path: c = silu(silu(coeffs)@Wc1)@Wc2   (M = 400000; persistent)
    fused_mlp_kernel<CDIM, false><<<148, 256, smem_c>>>(
        coeffs, Wc1, nullptr, Wc2, nullptr, cbuf, MR);

    // node path: h = silu(silu(x)@W1+b1)@W2+b2
    fused_mlp_kernel<HDIM, true><<<148, 256, smem_n>>>(
        x, W1, b1, W2, b2, hbuf, N_NODES);

    // zero aggregation buffer
    zero_kernel<<<((N_NODES*DDIM/4) + 255)/256, 256>>>((float4*)agg, N_NODES*DDIM/4);

    // edge stage: 2 edges per warp + v4 reduction segment-sum into agg
    edge_kernel<<<N_EDGES/16, 256>>>(cbuf, hbuf, rbfs, ei, agg);

    // out = agg @ Wu
    gemm_silu_kernel<32,128,64,false,false>
        <<<(N_NODES + 63)/64, dim3(32,8)>>>(agg, Wu, nullptr, out, N_NODES);
}

// round 10
// speedup vs baseline: 1.5193x; 1.0325x over previous
#include <cuda_runtime.h>
#include <cstdint>

#define N_NODES 50000
#define N_EDGES 800000
#define HDIM 128
#define DDIM 32
#define CDIM 64
#define RDIM 8

// ---- scratch (device globals; no allocation in kernel_launch) ----
__device__ float g_hbuf[N_NODES * DDIM];        // h                    [N,32]
__device__ float g_cbuf[N_NODES * RDIM * DDIM]; // c                    [N*R,32]
__device__ float g_agg[N_NODES * DDIM];         // segment_sum target   [N,32]

__device__ __forceinline__ float silu_f(float v) { return v / (1.0f + __expf(-v)); }

__device__ __forceinline__ uint32_t f2tf32(float f) {
    uint32_t u;
    asm("cvt.rna.tf32.f32 %0, %1;" : "=r"(u) : "f"(f));
    return u;
}

__device__ __forceinline__ void mma_tf32(float d[4], uint32_t a0, uint32_t a1,
                                         uint32_t a2, uint32_t a3,
                                         uint32_t b0, uint32_t b1) {
    asm volatile(
        "mma.sync.aligned.m16n8k8.row.col.f32.tf32.tf32.f32 "
        "{%0,%1,%2,%3},{%4,%5,%6,%7},{%8,%9},{%0,%1,%2,%3};"
        : "+f"(d[0]), "+f"(d[1]), "+f"(d[2]), "+f"(d[3])
        : "r"(a0), "r"(a1), "r"(a2), "r"(a3), "r"(b0), "r"(b1));
}

__device__ __forceinline__ void red_v4(float* p, float4 v) {
    asm volatile("red.global.add.v4.f32 [%0], {%1,%2,%3,%4};"
                 :: "l"(p), "f"(v.x), "f"(v.y), "f"(v.z), "f"(v.w) : "memory");
}

// Fused 2-layer MLP: Y[M,32] = silu(silu(A[M,K])@W1[K,128] (+b1)) @ W2[128,32] (+b2)
// 256 threads = 8 warps = 4 slabs of 16 rows; TWO warps per slab split the N dim:
//   phase 1: warp hh computes H cols [hh*64, hh*64+64)  (acc1 = 32 regs)
//   phase 2: warp hh computes Y cols [hh*16, hh*16+16)
// C1s is only [64][132] (34 KB) -> coeffs instantiation runs 2 blocks/SM.
template<int K, bool BIAS, int MINB>
__global__ void __launch_bounds__(256, MINB) fused_mlp_kernel(
    const float* __restrict__ A, const float* __restrict__ W1,
    const float* __restrict__ b1, const float* __restrict__ W2,
    const float* __restrict__ b2, float* __restrict__ Y, int M)
{
    extern __shared__ uint32_t sm[];
    uint32_t* W1s = sm;                        // [K][136] tf32
    uint32_t* W2s = W1s + K * 136;             // [128][40] tf32
    uint32_t* C1s = W2s + 128 * 40;            // [64][132] tf32
    float* b1s = (float*)(C1s + 64 * 132);     // [128]
    float* b2s = b1s + 128;                    // [32]

    const int tid = threadIdx.x;

    for (int i = tid; i < K * 128; i += 256) {
        int k = i >> 7, n = i & 127;
        W1s[k * 136 + n] = f2tf32(W1[i]);
    }
    for (int i = tid; i < 128 * 32; i += 256) {
        int k = i >> 5, n = i & 31;
        W2s[k * 40 + n] = f2tf32(W2[i]);
    }
    if (tid < 128) b1s[tid] = BIAS ? b1[tid] : 0.0f;
    if (tid < 32)  b2s[tid] = BIAS ? b2[tid] : 0.0f;
    __syncthreads();

    const int w = tid >> 5, lane = tid & 31;
    const int g = lane >> 2, tig = lane & 3;
    const int slab = w >> 1, hh = w & 1;
    const int srow0 = slab * 16 + g, srow1 = srow0 + 8;
    const int ntiles = (M + 63) / 64;

    for (int tile = blockIdx.x; tile < ntiles; tile += gridDim.x) {
        const int base = tile * 64 + slab * 16;
        const int r0 = base + g, r1 = base + g + 8;
        const bool v0 = r0 < M, v1 = r1 < M;
        const float* A0 = A + (size_t)r0 * K;
        const float* A1 = A + (size_t)r1 * K;

        // prefetch + convert ALL phase-1 A fragments (batched LDGs, high MLP)
        uint32_t af[K / 8][4];
#pragma unroll
        for (int kt = 0; kt < K / 8; kt++) {
            const int c0 = kt * 8 + tig;
            float f0 = v0 ? A0[c0]     : 0.0f;
            float f1 = v1 ? A1[c0]     : 0.0f;
            float f2 = v0 ? A0[c0 + 4] : 0.0f;
            float f3 = v1 ? A1[c0 + 4] : 0.0f;
            af[kt][0] = f2tf32(silu_f(f0));
            af[kt][1] = f2tf32(silu_f(f1));
            af[kt][2] = f2tf32(silu_f(f2));
            af[kt][3] = f2tf32(silu_f(f3));
        }

        // ---------------- phase 1: H[:, hh*64 : hh*64+64) ----------------
        float acc1[8][4];
#pragma unroll
        for (int nt = 0; nt < 8; nt++)
#pragma unroll
            for (int j = 0; j < 4; j++) acc1[nt][j] = 0.0f;

#pragma unroll
        for (int kt = 0; kt < K / 8; kt++) {
            const int c0 = kt * 8 + tig;
#pragma unroll
            for (int nt = 0; nt < 8; nt++) {
                const int col = hh * 64 + nt * 8 + g;
                uint32_t b0  = W1s[c0 * 136 + col];
                uint32_t b1r = W1s[(c0 + 4) * 136 + col];
                mma_tf32(acc1[nt], af[kt][0], af[kt][1], af[kt][2], af[kt][3], b0, b1r);
            }
        }

        // epilogue: bias + silu -> tf32 into C1s (this warp's 64-col half)
#pragma unroll
        for (int nt = 0; nt < 8; nt++) {
            int cA = hh * 64 + nt * 8 + 2 * tig;
            C1s[srow0 * 132 + cA]     = f2tf32(silu_f(acc1[nt][0] + b1s[cA]));
            C1s[srow0 * 132 + cA + 1] = f2tf32(silu_f(acc1[nt][1] + b1s[cA + 1]));
            C1s[srow1 * 132 + cA]     = f2tf32(silu_f(acc1[nt][2] + b1s[cA]));
            C1s[srow1 * 132 + cA + 1] = f2tf32(silu_f(acc1[nt][3] + b1s[cA + 1]));
        }
        __syncthreads();

        // ---------------- phase 2: Y[:, hh*16 : hh*16+16) ----------------
        float acc2[2][4];
#pragma unroll
        for (int nt = 0; nt < 2; nt++)
#pragma unroll
            for (int j = 0; j < 4; j++) acc2[nt][j] = 0.0f;

#pragma unroll
        for (int kt = 0; kt < 16; kt++) {
            const int c0 = kt * 8 + tig;
            uint32_t a0 = C1s[srow0 * 132 + c0];
            uint32_t a1 = C1s[srow1 * 132 + c0];
            uint32_t a2 = C1s[srow0 * 132 + c0 + 4];
            uint32_t a3 = C1s[srow1 * 132 + c0 + 4];
#pragma unroll
            for (int nt = 0; nt < 2; nt++) {
                const int colg = hh * 2 + nt;
                uint32_t b0  = W2s[c0 * 40 + colg * 8 + g];
                uint32_t b1r = W2s[(c0 + 4) * 40 + colg * 8 + g];
                mma_tf32(acc2[nt], a0, a1, a2, a3, b0, b1r);
            }
        }

#pragma unroll
        for (int nt = 0; nt < 2; nt++) {
            int cA = (hh * 2 + nt) * 8 + 2 * tig;
            if (v0) {
                Y[(size_t)r0 * 32 + cA]     = acc2[nt][0] + b2s[cA];
                Y[(size_t)r0 * 32 + cA + 1] = acc2[nt][1] + b2s[cA + 1];
            }
            if (v1) {
                Y[(size_t)r1 * 32 + cA]     = acc2[nt][2] + b2s[cA];
                Y[(size_t)r1 * 32 + cA + 1] = acc2[nt][3] + b2s[cA + 1];
            }
        }
        __syncthreads();   // phase-2 reads done before next tile overwrites C1s
    }
}

// FFMA GEMM (final up-projection): Y[M,NC] = A[M,K]@W[K,NC]
template<int K, int NC, int TM, bool SILU, bool BIAS>
__global__ void __launch_bounds__((NC/4)*(TM/8)) gemm_silu_kernel(
    const float* __restrict__ A, const float* __restrict__ W,
    const float* __restrict__ bias, float* __restrict__ Y, int M)
{
    __shared__ float As[TM][33];
    __shared__ float Ws[32][NC];
    const int tx = threadIdx.x;
    const int ty = threadIdx.y;
    const int TH = (NC/4)*(TM/8);
    const int tid = ty*(NC/4) + tx;
    const int m0 = blockIdx.x * TM;

    float acc[8][4];
#pragma unroll
    for (int i = 0; i < 8; i++)
#pragma unroll
        for (int j = 0; j < 4; j++) acc[i][j] = 0.0f;

    for (int k0 = 0; k0 < K; k0 += 32) {
        for (int idx = tid; idx < TM*8; idx += TH) {
            int row = idx >> 3, cc = idx & 7;
            float4 v = make_float4(0.f, 0.f, 0.f, 0.f);
            int m = m0 + row;
            if (m < M && (k0 + cc*4) < K) v = *(const float4*)(A + (size_t)m * K + k0 + cc*4);
            if (SILU) { v.x = silu_f(v.x); v.y = silu_f(v.y); v.z = silu_f(v.z); v.w = silu_f(v.w); }
            As[row][cc*4+0] = v.x; As[row][cc*4+1] = v.y;
            As[row][cc*4+2] = v.z; As[row][cc*4+3] = v.w;
        }
        for (int idx = tid; idx < 8*NC; idx += TH) {
            int kk = idx / (NC/4), cc = idx % (NC/4);
            float4 wv = make_float4(0.f,0.f,0.f,0.f);
            if (k0 + kk < K) wv = *(const float4*)(W + (size_t)(k0+kk)*NC + cc*4);
            *(float4*)&Ws[kk][cc*4] = wv;
        }
        __syncthreads();
#pragma unroll 8
        for (int kk = 0; kk < 32; kk++) {
            float4 wv = *(const float4*)&Ws[kk][tx*4];
#pragma unroll
            for (int i = 0; i < 8; i++) {
                float a = As[ty*8+i][kk];
                acc[i][0] = fmaf(a, wv.x, acc[i][0]);
                acc[i][1] = fmaf(a, wv.y, acc[i][1]);
                acc[i][2] = fmaf(a, wv.z, acc[i][2]);
                acc[i][3] = fmaf(a, wv.w, acc[i][3]);
            }
        }
        __syncthreads();
    }

    float4 bv = make_float4(0.f, 0.f, 0.f, 0.f);
    if (BIAS) bv = *(const float4*)(bias + tx*4);
#pragma unroll
    for (int i = 0; i < 8; i++) {
        int m = m0 + ty*8 + i;
        if (m < M) {
            float4 o = make_float4(acc[i][0]+bv.x, acc[i][1]+bv.y,
                                   acc[i][2]+bv.z, acc[i][3]+bv.w);
            *(float4*)(Y + (size_t)m * NC + tx*4) = o;
        }
    }
}

// TWO edges per warp, coalesced fp32 c loads (8 LDG.128 in flight per warp).
__global__ void edge_kernel(const float* __restrict__ c, const float* __restrict__ h,
                            const float* __restrict__ rbfs, const int* __restrict__ ei,
                            float* __restrict__ agg)
{
    int gwarp = blockIdx.x * 8 + (threadIdx.x >> 5);
    const int e0 = gwarp * 2;
    if (e0 >= N_EDGES) return;
    const int e1 = e0 + 1;
    const int lane = threadIdx.x & 31;
    const int grp = lane >> 3;          // rA = grp, rB = grp+4
    const int col4 = lane & 7;          // owns cols col4*4 .. col4*4+3

    const int src0 = ei[e0],           src1 = ei[e1];
    const int dst0 = ei[N_EDGES + e0], dst1 = ei[N_EDGES + e1];

    const float4* c4 = (const float4*)c;
    const size_t db0 = (size_t)dst0 * 64, sb0 = (size_t)src0 * 64;
    const size_t db1 = (size_t)dst1 * 64, sb1 = (size_t)src1 * 64;

    // issue ALL gathers up-front (8 independent LDG.128 per lane)
    float4 d00 = c4[db0 + lane], d01 = c4[db0 + 32 + lane];
    float4 s00 = c4[sb0 + lane], s01 = c4[sb0 + 32 + lane];
    float4 d10 = c4[db1 + lane], d11 = c4[db1 + 32 + lane];
    float4 s10 = c4[sb1 + lane], s11 = c4[sb1 + 32 + lane];

    // one coalesced rbf load covers both edges (rows e0,e1 are contiguous)
    float rv = (lane < 16) ? rbfs[(size_t)e0 * RDIM + lane] : 0.0f;

#pragma unroll
    for (int e = 0; e < 2; e++) {
        float4 da  = (e == 0) ? d00 : d10;
        float4 dbv = (e == 0) ? d01 : d11;
        float4 sa  = (e == 0) ? s00 : s10;
        float4 sbv = (e == 0) ? s01 : s11;

        float ceA[4], ceB[4];
        ceA[0] = da.x * (sa.x + 1.0f);   ceA[1] = da.y * (sa.y + 1.0f);
        ceA[2] = da.z * (sa.z + 1.0f);   ceA[3] = da.w * (sa.w + 1.0f);
        ceB[0] = dbv.x * (sbv.x + 1.0f); ceB[1] = dbv.y * (sbv.y + 1.0f);
        ceB[2] = dbv.z * (sbv.z + 1.0f); ceB[3] = dbv.w * (sbv.w + 1.0f);

        float ssA = 0.f, ssB = 0.f;
#pragma unroll
        for (int j = 0; j < 4; j++) { ssA = fmaf(ceA[j], ceA[j], ssA); ssB = fmaf(ceB[j], ceB[j], ssB); }
#pragma unroll
        for (int mask = 1; mask <= 4; mask <<= 1) {
            ssA += __shfl_xor_sync(0xffffffffu, ssA, mask);
            ssB += __shfl_xor_sync(0xffffffffu, ssB, mask);
        }
        float invA = rsqrtf(fmaxf(ssA, 1e-24f));
        float invB = rsqrtf(fmaxf(ssB, 1e-24f));

        float rbA = __shfl_sync(0xffffffffu, rv, e * 8 + grp);
        float rbB = __shfl_sync(0xffffffffu, rv, e * 8 + grp + 4);

        float sA = rbA * invA, sB = rbB * invB;
        float wl[4];
#pragma unroll
        for (int j = 0; j < 4; j++) wl[j] = ceA[j] * sA + ceB[j] * sB;
#pragma unroll
        for (int mask = 8; mask <= 16; mask <<= 1)
#pragma unroll
            for (int j = 0; j < 4; j++) wl[j] += __shfl_xor_sync(0xffffffffu, wl[j], mask);

        float sq = 0.f;
#pragma unroll
        for (int j = 0; j < 4; j++) sq = fmaf(wl[j], wl[j], sq);
#pragma unroll
        for (int mask = 1; mask <= 4; mask <<= 1)
            sq += __shfl_xor_sync(0xffffffffu, sq, mask);
        float invw = rsqrtf(fmaxf(sq, 1e-24f));

        if (grp == 0) {
            const int dste = (e == 0) ? dst0 : dst1;
            const int srce = (e == 0) ? src0 : src1;
            const float4 hv = *(const float4*)(h + (size_t)dste * DDIM + col4 * 4);
            float4 m = make_float4(hv.x * wl[0] * invw, hv.y * wl[1] * invw,
                                   hv.z * wl[2] * invw, hv.w * wl[3] * invw);
            red_v4(agg + (size_t)srce * DDIM + col4 * 4, m);
        }
    }
}

__global__ void zero_kernel(float4* p, int n4) {
    int i = blockIdx.x * blockDim.x + threadIdx.x;
    if (i < n4) p[i] = make_float4(0.f, 0.f, 0.f, 0.f);
}

extern "C" void kernel_launch(void* const* d_in, const int* in_sizes, int n_in,
                              void* d_out, int out_size)
{
    const float* x      = (const float*)d_in[0];
    const float* rbfs   = (const float*)d_in[1];
    const float* coeffs = (const float*)d_in[2];
    const float* W1     = (const float*)d_in[3];
    const float* b1     = (const float*)d_in[4];
    const float* W2     = (const float*)d_in[5];
    const float* b2     = (const float*)d_in[6];
    const float* Wc1    = (const float*)d_in[7];
    const float* Wc2    = (const float*)d_in[8];
    const float* Wu     = (const float*)d_in[9];
    const int*   ei     = (const int*)d_in[10];
    float* out = (float*)d_out;

    float *hbuf, *cbuf, *agg;
    cudaGetSymbolAddress((void**)&hbuf, g_hbuf);
    cudaGetSymbolAddress((void**)&cbuf, g_cbuf);
    cudaGetSymbolAddress((void**)&agg,  g_agg);

    const int MR = N_NODES * RDIM;

    // smem words: K*136 + 128*40 + 64*132 + 160
    const int smem_c = (CDIM * 136 + 128 * 40 + 64 * 132 + 160) * 4;   // ~90 KB
    const int smem_n = (HDIM * 136 + 128 * 40 + 64 * 132 + 160) * 4;   // ~124 KB
    cudaFuncSetAttribute(fused_mlp_kernel<CDIM, false, 2>,
                         cudaFuncAttributeMaxDynamicSharedMemorySize, smem_c);
    cudaFuncSetAttribute(fused_mlp_kernel<HDIM, true, 1>,
                         cudaFuncAttributeMaxDynamicSharedMemorySize, smem_n);

    // coeffs path: c = silu(silu(coeffs)@Wc1)@Wc2   (M = 400000; 2 blocks/SM)
    fused_mlp_kernel<CDIM, false, 2><<<296, 256, smem_c>>>(
        coeffs, Wc1, nullptr, Wc2, nullptr, cbuf, MR);

    // node path: h = silu(silu(x)@W1+b1)@W2+b2
    fused_mlp_kernel<HDIM, true, 1><<<148, 256, smem_n>>>(
        x, W1, b1, W2, b2, hbuf, N_NODES);

    // zero aggregation buffer
    zero_kernel<<<((N_NODES*DDIM/4) + 255)/256, 256>>>((float4*)agg, N_NODES*DDIM/4);

    // edge stage: 2 edges per warp + v4 reduction segment-sum into agg
    edge_kernel<<<N_EDGES/16, 256>>>(cbuf, hbuf, rbfs, ei, agg);

    // out = agg @ Wu
    gemm_silu_kernel<32,128,64,false,false>
        <<<(N_NODES + 63)/64, dim3(32,8)>>>(agg, Wu, nullptr, out, N_NODES);
}

// round 12
// speedup vs baseline: 1.5603x; 1.0270x over previous
#include <cuda_runtime.h>
#include <cstdint>

#define N_NODES 50000
#define N_EDGES 800000
#define HDIM 128
#define DDIM 32
#define CDIM 64
#define RDIM 8

#define TILES_C 6250            // ceil(400000/64)
#define TILES_N 782             // ceil(50000/64)
#define NB_C 244
#define NB_N 52                 // NB_C + NB_N = 296 = 2 blocks/SM

// ---- scratch (device globals; no allocation in kernel_launch) ----
__device__ float g_hbuf[N_NODES * DDIM];        // h                    [N,32]
__device__ float g_cbuf[N_NODES * RDIM * DDIM]; // c                    [N*R,32]
__device__ float g_agg[N_NODES * DDIM];         // segment_sum target   [N,32]

__device__ __forceinline__ float silu_f(float v) { return v / (1.0f + __expf(-v)); }

__device__ __forceinline__ uint32_t f2tf32(float f) {
    uint32_t u;
    asm("cvt.rna.tf32.f32 %0, %1;" : "=r"(u) : "f"(f));
    return u;
}

__device__ __forceinline__ void mma_tf32(float d[4], uint32_t a0, uint32_t a1,
                                         uint32_t a2, uint32_t a3,
                                         uint32_t b0, uint32_t b1) {
    asm volatile(
        "mma.sync.aligned.m16n8k8.row.col.f32.tf32.tf32.f32 "
        "{%0,%1,%2,%3},{%4,%5,%6,%7},{%8,%9},{%0,%1,%2,%3};"
        : "+f"(d[0]), "+f"(d[1]), "+f"(d[2]), "+f"(d[3])
        : "r"(a0), "r"(a1), "r"(a2), "r"(a3), "r"(b0), "r"(b1));
}

__device__ __forceinline__ void red_v4(float* p, float4 v) {
    asm volatile("red.global.add.v4.f32 [%0], {%1,%2,%3,%4};"
                 :: "l"(p), "f"(v.x), "f"(v.y), "f"(v.z), "f"(v.w) : "memory");
}

// Fused 2-layer MLP tile processor over tile range [t0,t1).
// K = KCHUNKS*64. W1s holds ONE 64-row K-chunk ([64][136], 34.8 KB); for
// KCHUNKS=2 chunks are (re)loaded inside the tile loop, with even/odd tiles
// alternating chunk order so only one reload happens per tile.
// Layout per block: 8 warps = 4 slabs x 16 rows; 2 warps/slab split N.
template<int KCHUNKS, bool BIAS>
__device__ void mlp_tiles(const float* __restrict__ A, const float* __restrict__ W1,
                          const float* __restrict__ b1, const float* __restrict__ W2,
                          const float* __restrict__ b2, float* __restrict__ Y,
                          int M, int t0, int t1, uint32_t* sm)
{
    constexpr int K = KCHUNKS * 64;
    uint32_t* W1s = sm;                        // [64][136] tf32 (one chunk)
    uint32_t* W2s = W1s + 64 * 136;            // [128][40] tf32
    uint32_t* C1s = W2s + 128 * 40;            // [64][132] tf32
    float* b1s = (float*)(C1s + 64 * 132);     // [128]
    float* b2s = b1s + 128;                    // [32]

    const int tid = threadIdx.x;

    for (int i = tid; i < 128 * 32; i += 256) {
        int k = i >> 5, n = i & 31;
        W2s[k * 40 + n] = f2tf32(W2[i]);
    }
    if (tid < 128) b1s[tid] = BIAS ? b1[tid] : 0.0f;
    if (tid < 32)  b2s[tid] = BIAS ? b2[tid] : 0.0f;
    if (KCHUNKS == 1) {
        for (int i = tid; i < 64 * 128; i += 256) {
            int k = i >> 7, n = i & 127;
            W1s[k * 136 + n] = f2tf32(W1[i]);
        }
    }
    __syncthreads();

    const int w = tid >> 5, lane = tid & 31;
    const int g = lane >> 2, tig = lane & 3;
    const int slab = w >> 1, hh = w & 1;
    const int srow0 = slab * 16 + g, srow1 = srow0 + 8;

    int cur = (KCHUNKS == 1) ? 0 : -1;   // chunk currently in W1s (block-uniform)

    for (int tile = t0; tile < t1; tile++) {
        const int base = tile * 64 + slab * 16;
        const int r0 = base + g, r1 = base + g + 8;
        const bool v0 = r0 < M, v1 = r1 < M;

        float acc1[8][4];
#pragma unroll
        for (int nt = 0; nt < 8; nt++)
#pragma unroll
            for (int j = 0; j < 4; j++) acc1[nt][j] = 0.0f;

#pragma unroll
        for (int kci = 0; kci < KCHUNKS; kci++) {
            const int kc = (KCHUNKS == 2 && (tile & 1)) ? (KCHUNKS - 1 - kci) : kci;

            // prefetch + convert this chunk's A fragments (LDGs issued before
            // the W1s-reload syncs so gather latency overlaps the weight copy)
            const float* A0 = A + (size_t)r0 * K + kc * 64;
            const float* A1 = A + (size_t)r1 * K + kc * 64;
            uint32_t af[8][4];
#pragma unroll
            for (int kt = 0; kt < 8; kt++) {
                const int c0 = kt * 8 + tig;
                float f0 = v0 ? A0[c0]     : 0.0f;
                float f1 = v1 ? A1[c0]     : 0.0f;
                float f2 = v0 ? A0[c0 + 4] : 0.0f;
                float f3 = v1 ? A1[c0 + 4] : 0.0f;
                af[kt][0] = f2tf32(silu_f(f0));
                af[kt][1] = f2tf32(silu_f(f1));
                af[kt][2] = f2tf32(silu_f(f2));
                af[kt][3] = f2tf32(silu_f(f3));
            }

            if (KCHUNKS > 1 && cur != kc) {
                __syncthreads();
                for (int i = tid; i < 64 * 128; i += 256) {
                    int k = i >> 7, n = i & 127;
                    W1s[k * 136 + n] = f2tf32(W1[(size_t)(kc * 64 + k) * 128 + n]);
                }
                __syncthreads();
                cur = kc;
            }

            // phase 1 mma: H[:, hh*64 : hh*64+64) over this K-chunk
#pragma unroll
            for (int kt = 0; kt < 8; kt++) {
                const int c0 = kt * 8 + tig;
#pragma unroll
                for (int nt = 0; nt < 8; nt++) {
                    const int col = hh * 64 + nt * 8 + g;
                    uint32_t b0  = W1s[c0 * 136 + col];
                    uint32_t b1r = W1s[(c0 + 4) * 136 + col];
                    mma_tf32(acc1[nt], af[kt][0], af[kt][1], af[kt][2], af[kt][3], b0, b1r);
                }
            }
        }

        // epilogue: bias + silu -> tf32 into C1s (this warp's 64-col half)
#pragma unroll
        for (int nt = 0; nt < 8; nt++) {
            int cA = hh * 64 + nt * 8 + 2 * tig;
            C1s[srow0 * 132 + cA]     = f2tf32(silu_f(acc1[nt][0] + b1s[cA]));
            C1s[srow0 * 132 + cA + 1] = f2tf32(silu_f(acc1[nt][1] + b1s[cA + 1]));
            C1s[srow1 * 132 + cA]     = f2tf32(silu_f(acc1[nt][2] + b1s[cA]));
            C1s[srow1 * 132 + cA + 1] = f2tf32(silu_f(acc1[nt][3] + b1s[cA + 1]));
        }
        __syncthreads();

        // phase 2: Y[:, hh*16 : hh*16+16)   (k-dim = H = 128 always)
        float acc2[2][4];
#pragma unroll
        for (int nt = 0; nt < 2; nt++)
#pragma unroll
            for (int j = 0; j < 4; j++) acc2[nt][j] = 0.0f;

#pragma unroll
        for (int kt = 0; kt < 16; kt++) {
            const int c0 = kt * 8 + tig;
            uint32_t a0 = C1s[srow0 * 132 + c0];
            uint32_t a1 = C1s[srow1 * 132 + c0];
            uint32_t a2 = C1s[srow0 * 132 + c0 + 4];
            uint32_t a3 = C1s[srow1 * 132 + c0 + 4];
#pragma unroll
            for (int nt = 0; nt < 2; nt++) {
                const int colg = hh * 2 + nt;
                uint32_t b0  = W2s[c0 * 40 + colg * 8 + g];
                uint32_t b1r = W2s[(c0 + 4) * 40 + colg * 8 + g];
                mma_tf32(acc2[nt], a0, a1, a2, a3, b0, b1r);
            }
        }

#pragma unroll
        for (int nt = 0; nt < 2; nt++) {
            int cA = (hh * 2 + nt) * 8 + 2 * tig;
            if (v0) {
                Y[(size_t)r0 * 32 + cA]     = acc2[nt][0] + b2s[cA];
                Y[(size_t)r0 * 32 + cA + 1] = acc2[nt][1] + b2s[cA + 1];
            }
            if (v1) {
                Y[(size_t)r1 * 32 + cA]     = acc2[nt][2] + b2s[cA];
                Y[(size_t)r1 * 32 + cA + 1] = acc2[nt][3] + b2s[cA + 1];
            }
        }
        __syncthreads();   // phase-2 reads done before next tile overwrites C1s
    }
}

// One launch does BOTH MLPs: blocks [0,NB_C) run the coeffs path, [NB_C,NB_C+NB_N)
// run the node path. 89.7 KB smem -> 2 blocks/SM for everyone.
__global__ void __launch_bounds__(256, 2) mlp_all_kernel(
    const float* __restrict__ coeffs, const float* __restrict__ Wc1,
    const float* __restrict__ Wc2,
    const float* __restrict__ x, const float* __restrict__ W1,
    const float* __restrict__ b1, const float* __restrict__ W2,
    const float* __restrict__ b2,
    float* __restrict__ cbuf, float* __restrict__ hbuf)
{
    extern __shared__ uint32_t sm[];
    if (blockIdx.x < NB_C) {
        const int bi = blockIdx.x;
        const int t0 = (int)((long long)bi * TILES_C / NB_C);
        const int t1 = (int)((long long)(bi + 1) * TILES_C / NB_C);
        mlp_tiles<1, false>(coeffs, Wc1, nullptr, Wc2, nullptr, cbuf,
                            N_NODES * RDIM, t0, t1, sm);
    } else {
        const int bi = blockIdx.x - NB_C;
        const int t0 = (int)((long long)bi * TILES_N / NB_N);
        const int t1 = (int)((long long)(bi + 1) * TILES_N / NB_N);
        mlp_tiles<2, true>(x, W1, b1, W2, b2, hbuf,
                           N_NODES, t0, t1, sm);
    }
}

// FFMA GEMM (final up-projection): Y[M,NC] = A[M,K]@W[K,NC]
template<int K, int NC, int TM, bool SILU, bool BIAS>
__global__ void __launch_bounds__((NC/4)*(TM/8)) gemm_silu_kernel(
    const float* __restrict__ A, const float* __restrict__ W,
    const float* __restrict__ bias, float* __restrict__ Y, int M)
{
    __shared__ float As[TM][33];
    __shared__ float Ws[32][NC];
    const int tx = threadIdx.x;
    const int ty = threadIdx.y;
    const int TH = (NC/4)*(TM/8);
    const int tid = ty*(NC/4) + tx;
    const int m0 = blockIdx.x * TM;

    float acc[8][4];
#pragma unroll
    for (int i = 0; i < 8; i++)
#pragma unroll
        for (int j = 0; j < 4; j++) acc[i][j] = 0.0f;

    for (int k0 = 0; k0 < K; k0 += 32) {
        for (int idx = tid; idx < TM*8; idx += TH) {
            int row = idx >> 3, cc = idx & 7;
            float4 v = make_float4(0.f, 0.f, 0.f, 0.f);
            int m = m0 + row;
            if (m < M && (k0 + cc*4) < K) v = *(const float4*)(A + (size_t)m * K + k0 + cc*4);
            if (SILU) { v.x = silu_f(v.x); v.y = silu_f(v.y); v.z = silu_f(v.z); v.w = silu_f(v.w); }
            As[row][cc*4+0] = v.x; As[row][cc*4+1] = v.y;
            As[row][cc*4+2] = v.z; As[row][cc*4+3] = v.w;
        }
        for (int idx = tid; idx < 8*NC; idx += TH) {
            int kk = idx / (NC/4), cc = idx % (NC/4);
            float4 wv = make_float4(0.f,0.f,0.f,0.f);
            if (k0 + kk < K) wv = *(const float4*)(W + (size_t)(k0+kk)*NC + cc*4);
            *(float4*)&Ws[kk][cc*4] = wv;
        }
        __syncthreads();
#pragma unroll 8
        for (int kk = 0; kk < 32; kk++) {
            float4 wv = *(const float4*)&Ws[kk][tx*4];
#pragma unroll
            for (int i = 0; i < 8; i++) {
                float a = As[ty*8+i][kk];
                acc[i][0] = fmaf(a, wv.x, acc[i][0]);
                acc[i][1] = fmaf(a, wv.y, acc[i][1]);
                acc[i][2] = fmaf(a, wv.z, acc[i][2]);
                acc[i][3] = fmaf(a, wv.w, acc[i][3]);
            }
        }
        __syncthreads();
    }

    float4 bv = make_float4(0.f, 0.f, 0.f, 0.f);
    if (BIAS) bv = *(const float4*)(bias + tx*4);
#pragma unroll
    for (int i = 0; i < 8; i++) {
        int m = m0 + ty*8 + i;
        if (m < M) {
            float4 o = make_float4(acc[i][0]+bv.x, acc[i][1]+bv.y,
                                   acc[i][2]+bv.z, acc[i][3]+bv.w);
            *(float4*)(Y + (size_t)m * NC + tx*4) = o;
        }
    }
}

// TWO edges per warp, coalesced fp32 c loads (8 LDG.128 in flight per warp).
__global__ void edge_kernel(const float* __restrict__ c, const float* __restrict__ h,
                            const float* __restrict__ rbfs, const int* __restrict__ ei,
                            float* __restrict__ agg)
{
    int gwarp = blockIdx.x * 8 + (threadIdx.x >> 5);
    const int e0 = gwarp * 2;
    if (e0 >= N_EDGES) return;
    const int e1 = e0 + 1;
    const int lane = threadIdx.x & 31;
    const int grp = lane >> 3;          // rA = grp, rB = grp+4
    const int col4 = lane & 7;          // owns cols col4*4 .. col4*4+3

    const int src0 = ei[e0],           src1 = ei[e1];
    const int dst0 = ei[N_EDGES + e0], dst1 = ei[N_EDGES + e1];

    const float4* c4 = (const float4*)c;
    const size_t db0 = (size_t)dst0 * 64, sb0 = (size_t)src0 * 64;
    const size_t db1 = (size_t)dst1 * 64, sb1 = (size_t)src1 * 64;

    // issue ALL gathers up-front (8 independent LDG.128 per lane)
    float4 d00 = c4[db0 + lane], d01 = c4[db0 + 32 + lane];
    float4 s00 = c4[sb0 + lane], s01 = c4[sb0 + 32 + lane];
    float4 d10 = c4[db1 + lane], d11 = c4[db1 + 32 + lane];
    float4 s10 = c4[sb1 + lane], s11 = c4[sb1 + 32 + lane];

    // one coalesced rbf load covers both edges (rows e0,e1 are contiguous)
    float rv = (lane < 16) ? rbfs[(size_t)e0 * RDIM + lane] : 0.0f;

#pragma unroll
    for (int e = 0; e < 2; e++) {
        float4 da  = (e == 0) ? d00 : d10;
        float4 dbv = (e == 0) ? d01 : d11;
        float4 sa  = (e == 0) ? s00 : s10;
        float4 sbv = (e == 0) ? s01 : s11;

        float ceA[4], ceB[4];
        ceA[0] = da.x * (sa.x + 1.0f);   ceA[1] = da.y * (sa.y + 1.0f);
        ceA[2] = da.z * (sa.z + 1.0f);   ceA[3] = da.w * (sa.w + 1.0f);
        ceB[0] = dbv.x * (sbv.x + 1.0f); ceB[1] = dbv.y * (sbv.y + 1.0f);
        ceB[2] = dbv.z * (sbv.z + 1.0f); ceB[3] = dbv.w * (sbv.w + 1.0f);

        float ssA = 0.f, ssB = 0.f;
#pragma unroll
        for (int j = 0; j < 4; j++) { ssA = fmaf(ceA[j], ceA[j], ssA); ssB = fmaf(ceB[j], ceB[j], ssB); }
#pragma unroll
        for (int mask = 1; mask <= 4; mask <<= 1) {
            ssA += __shfl_xor_sync(0xffffffffu, ssA, mask);
            ssB += __shfl_xor_sync(0xffffffffu, ssB, mask);
        }
        float invA = rsqrtf(fmaxf(ssA, 1e-24f));
        float invB = rsqrtf(fmaxf(ssB, 1e-24f));

        float rbA = __shfl_sync(0xffffffffu, rv, e * 8 + grp);
        float rbB = __shfl_sync(0xffffffffu, rv, e * 8 + grp + 4);

        float sA = rbA * invA, sB = rbB * invB;
        float wl[4];
#pragma unroll
        for (int j = 0; j < 4; j++) wl[j] = ceA[j] * sA + ceB[j] * sB;
#pragma unroll
        for (int mask = 8; mask <= 16; mask <<= 1)
#pragma unroll
            for (int j = 0; j < 4; j++) wl[j] += __shfl_xor_sync(0xffffffffu, wl[j], mask);

        float sq = 0.f;
#pragma unroll
        for (int j = 0; j < 4; j++) sq = fmaf(wl[j], wl[j], sq);
#pragma unroll
        for (int mask = 1; mask <= 4; mask <<= 1)
            sq += __shfl_xor_sync(0xffffffffu, sq, mask);
        float invw = rsqrtf(fmaxf(sq, 1e-24f));

        if (grp == 0) {
            const int dste = (e == 0) ? dst0 : dst1;
            const int srce = (e == 0) ? src0 : src1;
            const float4 hv = *(const float4*)(h + (size_t)dste * DDIM + col4 * 4);
            float4 m = make_float4(hv.x * wl[0] * invw, hv.y * wl[1] * invw,
                                   hv.z * wl[2] * invw, hv.w * wl[3] * invw);
            red_v4(agg + (size_t)srce * DDIM + col4 * 4, m);
        }
    }
}

__global__ void zero_kernel(float4* p, int n4) {
    int i = blockIdx.x * blockDim.x + threadIdx.x;
    if (i < n4) p[i] = make_float4(0.f, 0.f, 0.f, 0.f);
}

extern "C" void kernel_launch(void* const* d_in, const int* in_sizes, int n_in,
                              void* d_out, int out_size)
{
    const float* x      = (const float*)d_in[0];
    const float* rbfs   = (const float*)d_in[1];
    const float* coeffs = (const float*)d_in[2];
    const float* W1     = (const float*)d_in[3];
    const float* b1     = (const float*)d_in[4];
    const float* W2     = (const float*)d_in[5];
    const float* b2     = (const float*)d_in[6];
    const float* Wc1    = (const float*)d_in[7];
    const float* Wc2    = (const float*)d_in[8];
    const float* Wu     = (const float*)d_in[9];
    const int*   ei     = (const int*)d_in[10];
    float* out = (float*)d_out;

    float *hbuf, *cbuf, *agg;
    cudaGetSymbolAddress((void**)&hbuf, g_hbuf);
    cudaGetSymbolAddress((void**)&cbuf, g_cbuf);
    cudaGetSymbolAddress((void**)&agg,  g_agg);

    // smem: (64*136 + 128*40 + 64*132 + 160) words = 22432 * 4 = 89728 B
    const int smem_mlp = (64 * 136 + 128 * 40 + 64 * 132 + 160) * 4;
    cudaFuncSetAttribute(mlp_all_kernel,
                         cudaFuncAttributeMaxDynamicSharedMemorySize, smem_mlp);

    // both MLPs in one launch (coeffs blocks + node blocks), 2 blocks/SM
    mlp_all_kernel<<<NB_C + NB_N, 256, smem_mlp>>>(
        coeffs, Wc1, Wc2, x, W1, b1, W2, b2, cbuf, hbuf);

    // zero aggregation buffer
    zero_kernel<<<((N_NODES*DDIM/4) + 255)/256, 256>>>((float4*)agg, N_NODES*DDIM/4);

    // edge stage: 2 edges per warp + v4 reduction segment-sum into agg
    edge_kernel<<<N_EDGES/16, 256>>>(cbuf, hbuf, rbfs, ei, agg);

    // out = agg @ Wu
    gemm_silu_kernel<32,128,64,false,false>
        <<<(N_NODES + 63)/64, dim3(32,8)>>>(agg, Wu, nullptr, out, N_NODES);
}

// round 13
// speedup vs baseline: 1.8530x; 1.1876x over previous
#include <cuda_runtime.h>
#include <cstdint>

#define N_NODES 50000
#define N_EDGES 800000
#define HDIM 128
#define DDIM 32
#define CDIM 64
#define RDIM 8

#define TILES_C 6250            // ceil(400000/64)
#define TILES_N 782             // ceil(50000/64)
#define NB_C 232
#define NB_N 64                 // NB_C + NB_N = 296 = 2 blocks/SM; node tile ~2.2x coeffs tile

// ---- scratch (device globals; no allocation in kernel_launch) ----
__device__ float g_hbuf[N_NODES * DDIM];        // h                    [N,32]
__device__ float g_cbuf[N_NODES * RDIM * DDIM]; // c                    [N*R,32]
__device__ float g_agg[N_NODES * DDIM];         // segment_sum target   [N,32]

__device__ __forceinline__ float silu_f(float v) {
    // __fdividef: fast division regardless of compiler fast-math setting
    return __fdividef(v, 1.0f + __expf(-v));
}

__device__ __forceinline__ uint32_t f2tf32(float f) {
    uint32_t u;
    asm("cvt.rna.tf32.f32 %0, %1;" : "=r"(u) : "f"(f));
    return u;
}

__device__ __forceinline__ void mma_tf32(float d[4], uint32_t a0, uint32_t a1,
                                         uint32_t a2, uint32_t a3,
                                         uint32_t b0, uint32_t b1) {
    asm volatile(
        "mma.sync.aligned.m16n8k8.row.col.f32.tf32.tf32.f32 "
        "{%0,%1,%2,%3},{%4,%5,%6,%7},{%8,%9},{%0,%1,%2,%3};"
        : "+f"(d[0]), "+f"(d[1]), "+f"(d[2]), "+f"(d[3])
        : "r"(a0), "r"(a1), "r"(a2), "r"(a3), "r"(b0), "r"(b1));
}

__device__ __forceinline__ void red_v4(float* p, float4 v) {
    asm volatile("red.global.add.v4.f32 [%0], {%1,%2,%3,%4};"
                 :: "l"(p), "f"(v.x), "f"(v.y), "f"(v.z), "f"(v.w) : "memory");
}

// Fused 2-layer MLP tile processor over tile range [t0,t1).
// K = KCHUNKS*64. W1s holds ONE 64-row K-chunk ([64][136], 34.8 KB); for
// KCHUNKS=2 chunks are (re)loaded inside the tile loop, with even/odd tiles
// alternating chunk order so only one reload happens per tile.
// Layout per block: 8 warps = 4 slabs x 16 rows; 2 warps/slab split N.
template<int KCHUNKS, bool BIAS>
__device__ void mlp_tiles(const float* __restrict__ A, const float* __restrict__ W1,
                          const float* __restrict__ b1, const float* __restrict__ W2,
                          const float* __restrict__ b2, float* __restrict__ Y,
                          int M, int t0, int t1, uint32_t* sm)
{
    constexpr int K = KCHUNKS * 64;
    uint32_t* W1s = sm;                        // [64][136] tf32 (one chunk)
    uint32_t* W2s = W1s + 64 * 136;            // [128][40] tf32
    uint32_t* C1s = W2s + 128 * 40;            // [64][132] tf32
    float* b1s = (float*)(C1s + 64 * 132);     // [128]
    float* b2s = b1s + 128;                    // [32]

    const int tid = threadIdx.x;

    for (int i = tid; i < 128 * 32; i += 256) {
        int k = i >> 5, n = i & 31;
        W2s[k * 40 + n] = f2tf32(W2[i]);
    }
    if (tid < 128) b1s[tid] = BIAS ? b1[tid] : 0.0f;
    if (tid < 32)  b2s[tid] = BIAS ? b2[tid] : 0.0f;
    if (KCHUNKS == 1) {
        for (int i = tid; i < 64 * 128; i += 256) {
            int k = i >> 7, n = i & 127;
            W1s[k * 136 + n] = f2tf32(W1[i]);
        }
    }
    __syncthreads();

    const int w = tid >> 5, lane = tid & 31;
    const int g = lane >> 2, tig = lane & 3;
    const int slab = w >> 1, hh = w & 1;
    const int srow0 = slab * 16 + g, srow1 = srow0 + 8;

    int cur = (KCHUNKS == 1) ? 0 : -1;   // chunk currently in W1s (block-uniform)

    for (int tile = t0; tile < t1; tile++) {
        const int base = tile * 64 + slab * 16;
        const int r0 = base + g, r1 = base + g + 8;
        const bool v0 = r0 < M, v1 = r1 < M;

        float acc1[8][4];
#pragma unroll
        for (int nt = 0; nt < 8; nt++)
#pragma unroll
            for (int j = 0; j < 4; j++) acc1[nt][j] = 0.0f;

#pragma unroll
        for (int kci = 0; kci < KCHUNKS; kci++) {
            const int kc = (KCHUNKS == 2 && (tile & 1)) ? (KCHUNKS - 1 - kci) : kci;

            // prefetch + convert this chunk's A fragments (LDGs issued before
            // the W1s-reload syncs so gather latency overlaps the weight copy)
            const float* A0 = A + (size_t)r0 * K + kc * 64;
            const float* A1 = A + (size_t)r1 * K + kc * 64;
            uint32_t af[8][4];
#pragma unroll
            for (int kt = 0; kt < 8; kt++) {
                const int c0 = kt * 8 + tig;
                float f0 = v0 ? A0[c0]     : 0.0f;
                float f1 = v1 ? A1[c0]     : 0.0f;
                float f2 = v0 ? A0[c0 + 4] : 0.0f;
                float f3 = v1 ? A1[c0 + 4] : 0.0f;
                af[kt][0] = f2tf32(silu_f(f0));
                af[kt][1] = f2tf32(silu_f(f1));
                af[kt][2] = f2tf32(silu_f(f2));
                af[kt][3] = f2tf32(silu_f(f3));
            }

            if (KCHUNKS > 1 && cur != kc) {
                __syncthreads();
                for (int i = tid; i < 64 * 128; i += 256) {
                    int k = i >> 7, n = i & 127;
                    W1s[k * 136 + n] = f2tf32(W1[(size_t)(kc * 64 + k) * 128 + n]);
                }
                __syncthreads();
                cur = kc;
            }

            // phase 1 mma: H[:, hh*64 : hh*64+64) over this K-chunk
#pragma unroll
            for (int kt = 0; kt < 8; kt++) {
                const int c0 = kt * 8 + tig;
#pragma unroll
                for (int nt = 0; nt < 8; nt++) {
                    const int col = hh * 64 + nt * 8 + g;
                    uint32_t b0  = W1s[c0 * 136 + col];
                    uint32_t b1r = W1s[(c0 + 4) * 136 + col];
                    mma_tf32(acc1[nt], af[kt][0], af[kt][1], af[kt][2], af[kt][3], b0, b1r);
                }
            }
        }

        // epilogue: bias + silu -> tf32 into C1s (this warp's 64-col half)
#pragma unroll
        for (int nt = 0; nt < 8; nt++) {
            int cA = hh * 64 + nt * 8 + 2 * tig;
            C1s[srow0 * 132 + cA]     = f2tf32(silu_f(acc1[nt][0] + b1s[cA]));
            C1s[srow0 * 132 + cA + 1] = f2tf32(silu_f(acc1[nt][1] + b1s[cA + 1]));
            C1s[srow1 * 132 + cA]     = f2tf32(silu_f(acc1[nt][2] + b1s[cA]));
            C1s[srow1 * 132 + cA + 1] = f2tf32(silu_f(acc1[nt][3] + b1s[cA + 1]));
        }
        __syncthreads();

        // phase 2: Y[:, hh*16 : hh*16+16)   (k-dim = H = 128 always)
        float acc2[2][4];
#pragma unroll
        for (int nt = 0; nt < 2; nt++)
#pragma unroll
            for (int j = 0; j < 4; j++) acc2[nt][j] = 0.0f;

#pragma unroll
        for (int kt = 0; kt < 16; kt++) {
            const int c0 = kt * 8 + tig;
            uint32_t a0 = C1s[srow0 * 132 + c0];
            uint32_t a1 = C1s[srow1 * 132 + c0];
            uint32_t a2 = C1s[srow0 * 132 + c0 + 4];
            uint32_t a3 = C1s[srow1 * 132 + c0 + 4];
#pragma unroll
            for (int nt = 0; nt < 2; nt++) {
                const int colg = hh * 2 + nt;
                uint32_t b0  = W2s[c0 * 40 + colg * 8 + g];
                uint32_t b1r = W2s[(c0 + 4) * 40 + colg * 8 + g];
                mma_tf32(acc2[nt], a0, a1, a2, a3, b0, b1r);
            }
        }

#pragma unroll
        for (int nt = 0; nt < 2; nt++) {
            int cA = (hh * 2 + nt) * 8 + 2 * tig;
            if (v0) {
                Y[(size_t)r0 * 32 + cA]     = acc2[nt][0] + b2s[cA];
                Y[(size_t)r0 * 32 + cA + 1] = acc2[nt][1] + b2s[cA + 1];
            }
            if (v1) {
                Y[(size_t)r1 * 32 + cA]     = acc2[nt][2] + b2s[cA];
                Y[(size_t)r1 * 32 + cA + 1] = acc2[nt][3] + b2s[cA + 1];
            }
        }
        __syncthreads();   // phase-2 reads done before next tile overwrites C1s
    }
}

// One launch does BOTH MLPs + zeroes agg: blocks [0,NB_C) run the coeffs path,
// [NB_C,NB_C+NB_N) the node path. 89.7 KB smem -> 2 blocks/SM.
__global__ void __launch_bounds__(256, 2) mlp_all_kernel(
    const float* __restrict__ coeffs, const float* __restrict__ Wc1,
    const float* __restrict__ Wc2,
    const float* __restrict__ x, const float* __restrict__ W1,
    const float* __restrict__ b1, const float* __restrict__ W2,
    const float* __restrict__ b2,
    float* __restrict__ cbuf, float* __restrict__ hbuf,
    float4* __restrict__ aggz)
{
    extern __shared__ uint32_t sm[];

    // fused agg zeroing (independent of MLP work; edge launches after us)
    const float4 z4 = make_float4(0.f, 0.f, 0.f, 0.f);
    for (int i = blockIdx.x * 256 + threadIdx.x; i < N_NODES * DDIM / 4;
         i += (NB_C + NB_N) * 256)
        aggz[i] = z4;

    if (blockIdx.x < NB_C) {
        const int bi = blockIdx.x;
        const int t0 = (int)((long long)bi * TILES_C / NB_C);
        const int t1 = (int)((long long)(bi + 1) * TILES_C / NB_C);
        mlp_tiles<1, false>(coeffs, Wc1, nullptr, Wc2, nullptr, cbuf,
                            N_NODES * RDIM, t0, t1, sm);
    } else {
        const int bi = blockIdx.x - NB_C;
        const int t0 = (int)((long long)bi * TILES_N / NB_N);
        const int t1 = (int)((long long)(bi + 1) * TILES_N / NB_N);
        mlp_tiles<2, true>(x, W1, b1, W2, b2, hbuf,
                           N_NODES, t0, t1, sm);
    }
}

// FFMA GEMM (final up-projection): Y[M,NC] = A[M,K]@W[K,NC]
template<int K, int NC, int TM, bool SILU, bool BIAS>
__global__ void __launch_bounds__((NC/4)*(TM/8)) gemm_silu_kernel(
    const float* __restrict__ A, const float* __restrict__ W,
    const float* __restrict__ bias, float* __restrict__ Y, int M)
{
    __shared__ float As[TM][33];
    __shared__ float Ws[32][NC];
    const int tx = threadIdx.x;
    const int ty = threadIdx.y;
    const int TH = (NC/4)*(TM/8);
    const int tid = ty*(NC/4) + tx;
    const int m0 = blockIdx.x * TM;

    float acc[8][4];
#pragma unroll
    for (int i = 0; i < 8; i++)
#pragma unroll
        for (int j = 0; j < 4; j++) acc[i][j] = 0.0f;

    for (int k0 = 0; k0 < K; k0 += 32) {
        for (int idx = tid; idx < TM*8; idx += TH) {
            int row = idx >> 3, cc = idx & 7;
            float4 v = make_float4(0.f, 0.f, 0.f, 0.f);
            int m = m0 + row;
            if (m < M && (k0 + cc*4) < K) v = *(const float4*)(A + (size_t)m * K + k0 + cc*4);
            if (SILU) { v.x = silu_f(v.x); v.y = silu_f(v.y); v.z = silu_f(v.z); v.w = silu_f(v.w); }
            As[row][cc*4+0] = v.x; As[row][cc*4+1] = v.y;
            As[row][cc*4+2] = v.z; As[row][cc*4+3] = v.w;
        }
        for (int idx = tid; idx < 8*NC; idx += TH) {
            int kk = idx / (NC/4), cc = idx % (NC/4);
            float4 wv = make_float4(0.f,0.f,0.f,0.f);
            if (k0 + kk < K) wv = *(const float4*)(W + (size_t)(k0+kk)*NC + cc*4);
            *(float4*)&Ws[kk][cc*4] = wv;
        }
        __syncthreads();
#pragma unroll 8
        for (int kk = 0; kk < 32; kk++) {
            float4 wv = *(const float4*)&Ws[kk][tx*4];
#pragma unroll
            for (int i = 0; i < 8; i++) {
                float a = As[ty*8+i][kk];
                acc[i][0] = fmaf(a, wv.x, acc[i][0]);
                acc[i][1] = fmaf(a, wv.y, acc[i][1]);
                acc[i][2] = fmaf(a, wv.z, acc[i][2]);
                acc[i][3] = fmaf(a, wv.w, acc[i][3]);
            }
        }
        __syncthreads();
    }

    float4 bv = make_float4(0.f, 0.f, 0.f, 0.f);
    if (BIAS) bv = *(const float4*)(bias + tx*4);
#pragma unroll
    for (int i = 0; i < 8; i++) {
        int m = m0 + ty*8 + i;
        if (m < M) {
            float4 o = make_float4(acc[i][0]+bv.x, acc[i][1]+bv.y,
                                   acc[i][2]+bv.z, acc[i][3]+bv.w);
            *(float4*)(Y + (size_t)m * NC + tx*4) = o;
        }
    }
}

// TWO edges per warp, coalesced fp32 c loads (8 LDG.128 in flight per warp).
__global__ void edge_kernel(const float* __restrict__ c, const float* __restrict__ h,
                            const float* __restrict__ rbfs, const int* __restrict__ ei,
                            float* __restrict__ agg)
{
    int gwarp = blockIdx.x * 8 + (threadIdx.x >> 5);
    const int e0 = gwarp * 2;
    if (e0 >= N_EDGES) return;
    const int e1 = e0 + 1;
    const int lane = threadIdx.x & 31;
    const int grp = lane >> 3;          // rA = grp, rB = grp+4
    const int col4 = lane & 7;          // owns cols col4*4 .. col4*4+3

    const int src0 = ei[e0],           src1 = ei[e1];
    const int dst0 = ei[N_EDGES + e0], dst1 = ei[N_EDGES + e1];

    const float4* c4 = (const float4*)c;
    const size_t db0 = (size_t)dst0 * 64, sb0 = (size_t)src0 * 64;
    const size_t db1 = (size_t)dst1 * 64, sb1 = (size_t)src1 * 64;

    // issue ALL gathers up-front (8 independent LDG.128 per lane)
    float4 d00 = c4[db0 + lane], d01 = c4[db0 + 32 + lane];
    float4 s00 = c4[sb0 + lane], s01 = c4[sb0 + 32 + lane];
    float4 d10 = c4[db1 + lane], d11 = c4[db1 + 32 + lane];
    float4 s10 = c4[sb1 + lane], s11 = c4[sb1 + 32 + lane];

    // one coalesced rbf load covers both edges (rows e0,e1 are contiguous)
    float rv = (lane < 16) ? rbfs[(size_t)e0 * RDIM + lane] : 0.0f;

#pragma unroll
    for (int e = 0; e < 2; e++) {
        float4 da  = (e == 0) ? d00 : d10;
        float4 dbv = (e == 0) ? d01 : d11;
        float4 sa  = (e == 0) ? s00 : s10;
        float4 sbv = (e == 0) ? s01 : s11;

        float ceA[4], ceB[4];
        ceA[0] = da.x * (sa.x + 1.0f);   ceA[1] = da.y * (sa.y + 1.0f);
        ceA[2] = da.z * (sa.z + 1.0f);   ceA[3] = da.w * (sa.w + 1.0f);
        ceB[0] = dbv.x * (sbv.x + 1.0f); ceB[1] = dbv.y * (sbv.y + 1.0f);
        ceB[2] = dbv.z * (sbv.z + 1.0f); ceB[3] = dbv.w * (sbv.w + 1.0f);

        float ssA = 0.f, ssB = 0.f;
#pragma unroll
        for (int j = 0; j < 4; j++) { ssA = fmaf(ceA[j], ceA[j], ssA); ssB = fmaf(ceB[j], ceB[j], ssB); }
#pragma unroll
        for (int mask = 1; mask <= 4; mask <<= 1) {
            ssA += __shfl_xor_sync(0xffffffffu, ssA, mask);
            ssB += __shfl_xor_sync(0xffffffffu, ssB, mask);
        }
        float invA = rsqrtf(fmaxf(ssA, 1e-24f));
        float invB = rsqrtf(fmaxf(ssB, 1e-24f));

        float rbA = __shfl_sync(0xffffffffu, rv, e * 8 + grp);
        float rbB = __shfl_sync(0xffffffffu, rv, e * 8 + grp + 4);

        float sA = rbA * invA, sB = rbB * invB;
        float wl[4];
#pragma unroll
        for (int j = 0; j < 4; j++) wl[j] = ceA[j] * sA + ceB[j] * sB;
#pragma unroll
        for (int mask = 8; mask <= 16; mask <<= 1)
#pragma unroll
            for (int j = 0; j < 4; j++) wl[j] += __shfl_xor_sync(0xffffffffu, wl[j], mask);

        float sq = 0.f;
#pragma unroll
        for (int j = 0; j < 4; j++) sq = fmaf(wl[j], wl[j], sq);
#pragma unroll
        for (int mask = 1; mask <= 4; mask <<= 1)
            sq += __shfl_xor_sync(0xffffffffu, sq, mask);
        float invw = rsqrtf(fmaxf(sq, 1e-24f));

        if (grp == 0) {
            const int dste = (e == 0) ? dst0 : dst1;
            const int srce = (e == 0) ? src0 : src1;
            const float4 hv = *(const float4*)(h + (size_t)dste * DDIM + col4 * 4);
            float4 m = make_float4(hv.x * wl[0] * invw, hv.y * wl[1] * invw,
                                   hv.z * wl[2] * invw, hv.w * wl[3] * invw);
            red_v4(agg + (size_t)srce * DDIM + col4 * 4, m);
        }
    }
}

extern "C" void kernel_launch(void* const* d_in, const int* in_sizes, int n_in,
                              void* d_out, int out_size)
{
    const float* x      = (const float*)d_in[0];
    const float* rbfs   = (const float*)d_in[1];
    const float* coeffs = (const float*)d_in[2];
    const float* W1     = (const float*)d_in[3];
    const float* b1     = (const float*)d_in[4];
    const float* W2     = (const float*)d_in[5];
    const float* b2     = (const float*)d_in[6];
    const float* Wc1    = (const float*)d_in[7];
    const float* Wc2    = (const float*)d_in[8];
    const float* Wu     = (const float*)d_in[9];
    const int*   ei     = (const int*)d_in[10];
    float* out = (float*)d_out;

    float *hbuf, *cbuf, *agg;
    cudaGetSymbolAddress((void**)&hbuf, g_hbuf);
    cudaGetSymbolAddress((void**)&cbuf, g_cbuf);
    cudaGetSymbolAddress((void**)&agg,  g_agg);

    // smem: (64*136 + 128*40 + 64*132 + 160) words = 22432 * 4 = 89728 B
    const int smem_mlp = (64 * 136 + 128 * 40 + 64 * 132 + 160) * 4;
    cudaFuncSetAttribute(mlp_all_kernel,
                         cudaFuncAttributeMaxDynamicSharedMemorySize, smem_mlp);

    // both MLPs + agg zeroing in one launch, 2 blocks/SM
    mlp_all_kernel<<<NB_C + NB_N, 256, smem_mlp>>>(
        coeffs, Wc1, Wc2, x, W1, b1, W2, b2, cbuf, hbuf, (float4*)agg);

    // edge stage: 2 edges per warp + v4 reduction segment-sum into agg
    edge_kernel<<<N_EDGES/16, 256>>>(cbuf, hbuf, rbfs, ei, agg);

    // out = agg @ Wu
    gemm_silu_kernel<32,128,64,false,false>
        <<<(N_NODES + 63)/64, dim3(32,8)>>>(agg, Wu, nullptr, out, N_NODES);
}

// round 14
// speedup vs baseline: 2.5425x; 1.3721x over previous
#include <cuda_runtime.h>
#include <cuda_fp16.h>
#include <cstdint>

#define N_NODES 50000
#define N_EDGES 800000
#define HDIM 128
#define DDIM 32
#define CDIM 64
#define RDIM 8

#define TILES_C 6250            // ceil(400000/64)
#define TILES_N 782             // ceil(50000/64)
#define NB_C 366
#define NB_N 78                 // 444 = 3 blocks/SM; node tile ~1.7x coeffs tile

// ---- scratch (device globals; no allocation in kernel_launch) ----
__device__ float g_hbuf[N_NODES * DDIM];        // h                    [N,32]
__device__ float g_cbuf[N_NODES * RDIM * DDIM]; // c                    [N*R,32]
__device__ float g_agg[N_NODES * DDIM];         // segment_sum target   [N,32]

__device__ __forceinline__ float silu_f(float v) {
    return __fdividef(v, 1.0f + __expf(-v));
}

// pack two fp32 into f16x2: {lo, hi}
__device__ __forceinline__ uint32_t packh2(float lo, float hi) {
    uint32_t r;
    asm("cvt.rn.f16x2.f32 %0, %1, %2;" : "=r"(r) : "f"(hi), "f"(lo));
    return r;
}

__device__ __forceinline__ void mma_f16(float d[4], uint32_t a0, uint32_t a1,
                                        uint32_t a2, uint32_t a3,
                                        uint32_t b0, uint32_t b1) {
    asm volatile(
        "mma.sync.aligned.m16n8k16.row.col.f32.f16.f16.f32 "
        "{%0,%1,%2,%3},{%4,%5,%6,%7},{%8,%9},{%0,%1,%2,%3};"
        : "+f"(d[0]), "+f"(d[1]), "+f"(d[2]), "+f"(d[3])
        : "r"(a0), "r"(a1), "r"(a2), "r"(a3), "r"(b0), "r"(b1));
}

__device__ __forceinline__ void red_v4(float* p, float4 v) {
    asm volatile("red.global.add.v4.f32 [%0], {%1,%2,%3,%4};"
                 :: "l"(p), "f"(v.x), "f"(v.y), "f"(v.z), "f"(v.w) : "memory");
}

// Fused 2-layer MLP (fp16 tensor-core): Y = silu(silu(A)@W1 (+b1)) @ W2 (+b2).
// mma.m16n8k16.f16, fp32 accum. 8 warps = 4 slabs x 16 rows, 2 warps/slab split N.
// W1p: uint2[(K/4)][132]  — row kg*4+tig holds {h2(W1[16kg+2t],[+1]), h2([+8],[+9])}[col]
// W2p: uint2[32][36]      — same k-pair packing, n = 0..31
// C1h: u32[64][68]        — H as half2 (c,c+1) pairs
template<int K, bool BIAS>
__device__ void mlp_tiles(const float* __restrict__ A, const float* __restrict__ W1,
                          const float* __restrict__ b1, const float* __restrict__ W2,
                          const float* __restrict__ b2, float* __restrict__ Y,
                          int M, int t0, int t1, uint32_t* sm)
{
    constexpr int R1 = K / 4;                  // W1p rows
    uint2* W1p = (uint2*)sm;                   // [R1][132]
    uint2* W2p = W1p + R1 * 132;               // [32][36]
    uint32_t* C1h = (uint32_t*)(W2p + 32 * 36); // [64][68]
    float* b1s = (float*)(C1h + 64 * 68);      // [128]
    float* b2s = b1s + 128;                    // [32]

    const int tid = threadIdx.x;

    // W1 -> packed half2 k-pairs
    for (int i = tid; i < R1 * 128; i += 256) {
        int r = i >> 7, col = i & 127;
        int kg = r >> 2, tg = r & 3;
        int k0 = kg * 16 + 2 * tg;
        float w00 = W1[(size_t)k0 * 128 + col];
        float w01 = W1[(size_t)(k0 + 1) * 128 + col];
        float w10 = W1[(size_t)(k0 + 8) * 128 + col];
        float w11 = W1[(size_t)(k0 + 9) * 128 + col];
        W1p[r * 132 + col] = make_uint2(packh2(w00, w01), packh2(w10, w11));
    }
    // W2 -> packed half2 k-pairs
    for (int i = tid; i < 32 * 32; i += 256) {
        int r = i >> 5, n = i & 31;
        int kg = r >> 2, tg = r & 3;
        int k0 = kg * 16 + 2 * tg;
        float w00 = W2[(size_t)k0 * 32 + n];
        float w01 = W2[(size_t)(k0 + 1) * 32 + n];
        float w10 = W2[(size_t)(k0 + 8) * 32 + n];
        float w11 = W2[(size_t)(k0 + 9) * 32 + n];
        W2p[r * 36 + n] = make_uint2(packh2(w00, w01), packh2(w10, w11));
    }
    if (tid < 128) b1s[tid] = BIAS ? b1[tid] : 0.0f;
    if (tid < 32)  b2s[tid] = BIAS ? b2[tid] : 0.0f;
    __syncthreads();

    const int w = tid >> 5, lane = tid & 31;
    const int g = lane >> 2, tig = lane & 3;
    const int slab = w >> 1, hh = w & 1;
    const int srow0 = slab * 16 + g, srow1 = srow0 + 8;

    for (int tile = t0; tile < t1; tile++) {
        const int base = tile * 64 + slab * 16;
        const int r0 = base + g, r1 = base + g + 8;
        const bool v0 = r0 < M, v1 = r1 < M;
        const float* A0 = A + (size_t)r0 * K;
        const float* A1 = A + (size_t)r1 * K;

        float acc1[8][4];
#pragma unroll
        for (int nt = 0; nt < 8; nt++)
#pragma unroll
            for (int j = 0; j < 4; j++) acc1[nt][j] = 0.0f;

        const float2 z2 = make_float2(0.f, 0.f);
        // process K in halves of 64 (4 k16-groups) to cap af registers at 16
#pragma unroll
        for (int h = 0; h < K / 64; h++) {
            uint32_t af[4][4];
#pragma unroll
            for (int q = 0; q < 4; q++) {
                const int kb = h * 64 + q * 16 + 2 * tig;
                float2 p00 = v0 ? *(const float2*)(A0 + kb)     : z2;
                float2 p01 = v0 ? *(const float2*)(A0 + kb + 8) : z2;
                float2 p10 = v1 ? *(const float2*)(A1 + kb)     : z2;
                float2 p11 = v1 ? *(const float2*)(A1 + kb + 8) : z2;
                af[q][0] = packh2(silu_f(p00.x), silu_f(p00.y));
                af[q][1] = packh2(silu_f(p10.x), silu_f(p10.y));
                af[q][2] = packh2(silu_f(p01.x), silu_f(p01.y));
                af[q][3] = packh2(silu_f(p11.x), silu_f(p11.y));
            }
#pragma unroll
            for (int q = 0; q < 4; q++) {
                const int kg = h * 4 + q;
                const int brow = (kg * 4 + tig) * 132;
#pragma unroll
                for (int nt = 0; nt < 8; nt++) {
                    const int col = hh * 64 + nt * 8 + g;
                    uint2 bb = W1p[brow + col];
                    mma_f16(acc1[nt], af[q][0], af[q][1], af[q][2], af[q][3],
                            bb.x, bb.y);
                }
            }
        }

        // epilogue: bias + silu -> half2 into C1h (this warp's 64-col half)
#pragma unroll
        for (int nt = 0; nt < 8; nt++) {
            const int cA = hh * 64 + nt * 8 + 2 * tig;
            const int cp = hh * 32 + nt * 4 + tig;
            C1h[srow0 * 68 + cp] = packh2(silu_f(acc1[nt][0] + b1s[cA]),
                                          silu_f(acc1[nt][1] + b1s[cA + 1]));
            C1h[srow1 * 68 + cp] = packh2(silu_f(acc1[nt][2] + b1s[cA]),
                                          silu_f(acc1[nt][3] + b1s[cA + 1]));
        }
        __syncthreads();

        // phase 2: Y[:, hh*16 : hh*16+16)  (k = 128)
        float acc2[2][4];
#pragma unroll
        for (int nt = 0; nt < 2; nt++)
#pragma unroll
            for (int j = 0; j < 4; j++) acc2[nt][j] = 0.0f;

#pragma unroll
        for (int kg = 0; kg < 8; kg++) {
            uint32_t a0 = C1h[srow0 * 68 + kg * 8 + tig];
            uint32_t a1 = C1h[srow1 * 68 + kg * 8 + tig];
            uint32_t a2 = C1h[srow0 * 68 + kg * 8 + tig + 4];
            uint32_t a3 = C1h[srow1 * 68 + kg * 8 + tig + 4];
            const int brow = (kg * 4 + tig) * 36;
#pragma unroll
            for (int nt = 0; nt < 2; nt++) {
                const int n = (hh * 2 + nt) * 8 + g;
                uint2 bb = W2p[brow + n];
                mma_f16(acc2[nt], a0, a1, a2, a3, bb.x, bb.y);
            }
        }

#pragma unroll
        for (int nt = 0; nt < 2; nt++) {
            const int cA = (hh * 2 + nt) * 8 + 2 * tig;
            if (v0) {
                Y[(size_t)r0 * 32 + cA]     = acc2[nt][0] + b2s[cA];
                Y[(size_t)r0 * 32 + cA + 1] = acc2[nt][1] + b2s[cA + 1];
            }
            if (v1) {
                Y[(size_t)r1 * 32 + cA]     = acc2[nt][2] + b2s[cA];
                Y[(size_t)r1 * 32 + cA + 1] = acc2[nt][3] + b2s[cA + 1];
            }
        }
        __syncthreads();   // phase-2 reads done before next tile overwrites C1h
    }
}

// One launch: both MLPs + agg zeroing. 61 KB smem, <=85 regs -> 3 blocks/SM.
__global__ void __launch_bounds__(256, 3) mlp_all_kernel(
    const float* __restrict__ coeffs, const float* __restrict__ Wc1,
    const float* __restrict__ Wc2,
    const float* __restrict__ x, const float* __restrict__ W1,
    const float* __restrict__ b1, const float* __restrict__ W2,
    const float* __restrict__ b2,
    float* __restrict__ cbuf, float* __restrict__ hbuf,
    float4* __restrict__ aggz)
{
    extern __shared__ uint32_t sm[];

    const float4 z4 = make_float4(0.f, 0.f, 0.f, 0.f);
    for (int i = blockIdx.x * 256 + threadIdx.x; i < N_NODES * DDIM / 4;
         i += (NB_C + NB_N) * 256)
        aggz[i] = z4;

    if (blockIdx.x < NB_C) {
        const int bi = blockIdx.x;
        const int t0 = (int)((long long)bi * TILES_C / NB_C);
        const int t1 = (int)((long long)(bi + 1) * TILES_C / NB_C);
        mlp_tiles<CDIM, false>(coeffs, Wc1, nullptr, Wc2, nullptr, cbuf,
                               N_NODES * RDIM, t0, t1, sm);
    } else {
        const int bi = blockIdx.x - NB_C;
        const int t0 = (int)((long long)bi * TILES_N / NB_N);
        const int t1 = (int)((long long)(bi + 1) * TILES_N / NB_N);
        mlp_tiles<HDIM, true>(x, W1, b1, W2, b2, hbuf,
                              N_NODES, t0, t1, sm);
    }
}

// FFMA GEMM (final up-projection): Y[M,NC] = A[M,K]@W[K,NC]
template<int K, int NC, int TM, bool SILU, bool BIAS>
__global__ void __launch_bounds__((NC/4)*(TM/8)) gemm_silu_kernel(
    const float* __restrict__ A, const float* __restrict__ W,
    const float* __restrict__ bias, float* __restrict__ Y, int M)
{
    __shared__ float As[TM][33];
    __shared__ float Ws[32][NC];
    const int tx = threadIdx.x;
    const int ty = threadIdx.y;
    const int TH = (NC/4)*(TM/8);
    const int tid = ty*(NC/4) + tx;
    const int m0 = blockIdx.x * TM;

    float acc[8][4];
#pragma unroll
    for (int i = 0; i < 8; i++)
#pragma unroll
        for (int j = 0; j < 4; j++) acc[i][j] = 0.0f;

    for (int k0 = 0; k0 < K; k0 += 32) {
        for (int idx = tid; idx < TM*8; idx += TH) {
            int row = idx >> 3, cc = idx & 7;
            float4 v = make_float4(0.f, 0.f, 0.f, 0.f);
            int m = m0 + row;
            if (m < M && (k0 + cc*4) < K) v = *(const float4*)(A + (size_t)m * K + k0 + cc*4);
            if (SILU) { v.x = silu_f(v.x); v.y = silu_f(v.y); v.z = silu_f(v.z); v.w = silu_f(v.w); }
            As[row][cc*4+0] = v.x; As[row][cc*4+1] = v.y;
            As[row][cc*4+2] = v.z; As[row][cc*4+3] = v.w;
        }
        for (int idx = tid; idx < 8*NC; idx += TH) {
            int kk = idx / (NC/4), cc = idx % (NC/4);
            float4 wv = make_float4(0.f,0.f,0.f,0.f);
            if (k0 + kk < K) wv = *(const float4*)(W + (size_t)(k0+kk)*NC + cc*4);
            *(float4*)&Ws[kk][cc*4] = wv;
        }
        __syncthreads();
#pragma unroll 8
        for (int kk = 0; kk < 32; kk++) {
            float4 wv = *(const float4*)&Ws[kk][tx*4];
#pragma unroll
            for (int i = 0; i < 8; i++) {
                float a = As[ty*8+i][kk];
                acc[i][0] = fmaf(a, wv.x, acc[i][0]);
                acc[i][1] = fmaf(a, wv.y, acc[i][1]);
                acc[i][2] = fmaf(a, wv.z, acc[i][2]);
                acc[i][3] = fmaf(a, wv.w, acc[i][3]);
            }
        }
        __syncthreads();
    }

    float4 bv = make_float4(0.f, 0.f, 0.f, 0.f);
    if (BIAS) bv = *(const float4*)(bias + tx*4);
#pragma unroll
    for (int i = 0; i < 8; i++) {
        int m = m0 + ty*8 + i;
        if (m < M) {
            float4 o = make_float4(acc[i][0]+bv.x, acc[i][1]+bv.y,
                                   acc[i][2]+bv.z, acc[i][3]+bv.w);
            *(float4*)(Y + (size_t)m * NC + tx*4) = o;
        }
    }
}

// TWO edges per warp, coalesced fp32 c loads (8 LDG.128 in flight per warp).
__global__ void edge_kernel(const float* __restrict__ c, const float* __restrict__ h,
                            const float* __restrict__ rbfs, const int* __restrict__ ei,
                            float* __restrict__ agg)
{
    int gwarp = blockIdx.x * 8 + (threadIdx.x >> 5);
    const int e0 = gwarp * 2;
    if (e0 >= N_EDGES) return;
    const int e1 = e0 + 1;
    const int lane = threadIdx.x & 31;
    const int grp = lane >> 3;          // rA = grp, rB = grp+4
    const int col4 = lane & 7;          // owns cols col4*4 .. col4*4+3

    const int src0 = ei[e0],           src1 = ei[e1];
    const int dst0 = ei[N_EDGES + e0], dst1 = ei[N_EDGES + e1];

    const float4* c4 = (const float4*)c;
    const size_t db0 = (size_t)dst0 * 64, sb0 = (size_t)src0 * 64;
    const size_t db1 = (size_t)dst1 * 64, sb1 = (size_t)src1 * 64;

    float4 d00 = c4[db0 + lane], d01 = c4[db0 + 32 + lane];
    float4 s00 = c4[sb0 + lane], s01 = c4[sb0 + 32 + lane];
    float4 d10 = c4[db1 + lane], d11 = c4[db1 + 32 + lane];
    float4 s10 = c4[sb1 + lane], s11 = c4[sb1 + 32 + lane];

    float rv = (lane < 16) ? rbfs[(size_t)e0 * RDIM + lane] : 0.0f;

#pragma unroll
    for (int e = 0; e < 2; e++) {
        float4 da  = (e == 0) ? d00 : d10;
        float4 dbv = (e == 0) ? d01 : d11;
        float4 sa  = (e == 0) ? s00 : s10;
        float4 sbv = (e == 0) ? s01 : s11;

        float ceA[4], ceB[4];
        ceA[0] = da.x * (sa.x + 1.0f);   ceA[1] = da.y * (sa.y + 1.0f);
        ceA[2] = da.z * (sa.z + 1.0f);   ceA[3] = da.w * (sa.w + 1.0f);
        ceB[0] = dbv.x * (sbv.x + 1.0f); ceB[1] = dbv.y * (sbv.y + 1.0f);
        ceB[2] = dbv.z * (sbv.z + 1.0f); ceB[3] = dbv.w * (sbv.w + 1.0f);

        float ssA = 0.f, ssB = 0.f;
#pragma unroll
        for (int j = 0; j < 4; j++) { ssA = fmaf(ceA[j], ceA[j], ssA); ssB = fmaf(ceB[j], ceB[j], ssB); }
#pragma unroll
        for (int mask = 1; mask <= 4; mask <<= 1) {
            ssA += __shfl_xor_sync(0xffffffffu, ssA, mask);
            ssB += __shfl_xor_sync(0xffffffffu, ssB, mask);
        }
        float invA = rsqrtf(fmaxf(ssA, 1e-24f));
        float invB = rsqrtf(fmaxf(ssB, 1e-24f));

        float rbA = __shfl_sync(0xffffffffu, rv, e * 8 + grp);
        float rbB = __shfl_sync(0xffffffffu, rv, e * 8 + grp + 4);

        float sA = rbA * invA, sB = rbB * invB;
        float wl[4];
#pragma unroll
        for (int j = 0; j < 4; j++) wl[j] = ceA[j] * sA + ceB[j] * sB;
#pragma unroll
        for (int mask = 8; mask <= 16; mask <<= 1)
#pragma unroll
            for (int j = 0; j < 4; j++) wl[j] += __shfl_xor_sync(0xffffffffu, wl[j], mask);

        float sq = 0.f;
#pragma unroll
        for (int j = 0; j < 4; j++) sq = fmaf(wl[j], wl[j], sq);
#pragma unroll
        for (int mask = 1; mask <= 4; mask <<= 1)
            sq += __shfl_xor_sync(0xffffffffu, sq, mask);
        float invw = rsqrtf(fmaxf(sq, 1e-24f));

        if (grp == 0) {
            const int dste = (e == 0) ? dst0 : dst1;
            const int srce = (e == 0) ? src0 : src1;
            const float4 hv = *(const float4*)(h + (size_t)dste * DDIM + col4 * 4);
            float4 m = make_float4(hv.x * wl[0] * invw, hv.y * wl[1] * invw,
                                   hv.z * wl[2] * invw, hv.w * wl[3] * invw);
            red_v4(agg + (size_t)srce * DDIM + col4 * 4, m);
        }
    }
}

extern "C" void kernel_launch(void* const* d_in, const int* in_sizes, int n_in,
                              void* d_out, int out_size)
{
    const float* x      = (const float*)d_in[0];
    const float* rbfs   = (const float*)d_in[1];
    const float* coeffs = (const float*)d_in[2];
    const float* W1     = (const float*)d_in[3];
    const float* b1     = (const float*)d_in[4];
    const float* W2     = (const float*)d_in[5];
    const float* b2     = (const float*)d_in[6];
    const float* Wc1    = (const float*)d_in[7];
    const float* Wc2    = (const float*)d_in[8];
    const float* Wu     = (const float*)d_in[9];
    const int*   ei     = (const int*)d_in[10];
    float* out = (float*)d_out;

    float *hbuf, *cbuf, *agg;
    cudaGetSymbolAddress((void**)&hbuf, g_hbuf);
    cudaGetSymbolAddress((void**)&cbuf, g_cbuf);
    cudaGetSymbolAddress((void**)&agg,  g_agg);

    // smem (node max): (32*132 + 32*36) uint2 *8B + 64*68*4 + 160*4 = 61056 B
    const int smem_mlp = (32 * 132 + 32 * 36) * 8 + 64 * 68 * 4 + 160 * 4;
    cudaFuncSetAttribute(mlp_all_kernel,
                         cudaFuncAttributeMaxDynamicSharedMemorySize, smem_mlp);

    // both MLPs + agg zeroing in one launch, 3 blocks/SM
    mlp_all_kernel<<<NB_C + NB_N, 256, smem_mlp>>>(
        coeffs, Wc1, Wc2, x, W1, b1, W2, b2, cbuf, hbuf, (float4*)agg);

    // edge stage: 2 edges per warp + v4 reduction segment-sum into agg
    edge_kernel<<<N_EDGES/16, 256>>>(cbuf, hbuf, rbfs, ei, agg);

    // out = agg @ Wu
    gemm_silu_kernel<32,128,64,false,false>
        <<<(N_NODES + 63)/64, dim3(32,8)>>>(agg, Wu, nullptr, out, N_NODES);
}